// round 1
// baseline (speedup 1.0000x reference)
#include <cuda_runtime.h>

#define BWIN 2048
#define NTOK 64
#define DIM  256
#define HEADS 8
#define HD   32
#define NW   64

// ---- scratch (device globals; no allocations allowed) ----
__device__ float g_q [BWIN*HEADS*NTOK*HD];   // (b,h,n,d)
__device__ float g_k [BWIN*HEADS*NTOK*HD];
__device__ float g_v [BWIN*HEADS*NTOK*HD];
__device__ float g_ao[BWIN*NTOK*DIM];        // (b,n,c) attention output
__device__ float g_bias  [HEADS*NTOK*NTOK];  // (h,i,j) CPB bias
__device__ float g_invtau[HEADS*NTOK*NTOK];  // 1/max(tau,0.01)

// ============================================================
// Kernel 1: precompute CPB bias MLP + inv-tau tables
// ============================================================
__global__ void bias_kernel(const float* __restrict__ w1, const float* __restrict__ b1,
                            const float* __restrict__ w2, const float* __restrict__ b2,
                            const float* __restrict__ tau, const float* __restrict__ lri)
{
    int idx = blockIdx.x * blockDim.x + threadIdx.x;   // 0..4095 = (i,j)
    if (idx >= NTOK*NTOK) return;
    float r0 = lri[idx*2 + 0];
    float r1 = lri[idx*2 + 1];
    float acc[HEADS];
    #pragma unroll
    for (int h = 0; h < HEADS; h++) acc[h] = 0.f;
    for (int k = 0; k < 256; k++) {
        float hk = fmaxf(r0 * w1[k] + r1 * w1[256 + k] + b1[k], 0.f);
        #pragma unroll
        for (int h = 0; h < HEADS; h++) acc[h] += hk * w2[k*HEADS + h];
    }
    #pragma unroll
    for (int h = 0; h < HEADS; h++) {
        g_bias[h*NTOK*NTOK + idx] = acc[h] + b2[h];
        g_invtau[h*NTOK*NTOK + idx] = 1.0f / fmaxf(tau[h*NTOK*NTOK + idx], 0.01f);
    }
}

// ============================================================
// Kernel 2: tiled SGEMM 128x128x8, 256 threads, 8x8 microtile
//   mode 0: Q  = x  @ Wq  + bq, *scale, scatter to (b,h,n,d)
//   mode 1: KV = KV @ Wkv + bkv, scatter to g_k / g_v
//   mode 2: out = g_ao @ Wp + bp, row-major to D
// ============================================================
__global__ void __launch_bounds__(256) sgemm_kernel(
    const float* __restrict__ A, const float* __restrict__ Bm,
    const float* __restrict__ bias, float* __restrict__ D,
    int ldb, int mode)
{
    __shared__ float As[8][128];
    __shared__ float Bs[8][128];

    const float* Ap = (mode == 2) ? g_ao : A;
    int tid = threadIdx.x;
    int row0 = blockIdx.y * 128;
    int col0 = blockIdx.x * 128;
    int ty = tid >> 4, tx = tid & 15;

    float acc[8][8];
    #pragma unroll
    for (int i = 0; i < 8; i++)
        #pragma unroll
        for (int j = 0; j < 8; j++) acc[i][j] = 0.f;

    int ar_ = tid >> 1;
    int ac_ = (tid & 1) * 4;
    int brr = tid >> 5;
    int bcc = (tid & 31) * 4;

    for (int k0 = 0; k0 < DIM; k0 += 8) {
        float4 a = *(const float4*)(Ap + (size_t)(row0 + ar_) * DIM + k0 + ac_);
        As[ac_ + 0][ar_] = a.x;
        As[ac_ + 1][ar_] = a.y;
        As[ac_ + 2][ar_] = a.z;
        As[ac_ + 3][ar_] = a.w;
        *(float4*)&Bs[brr][bcc] = *(const float4*)(Bm + (size_t)(k0 + brr) * ldb + col0 + bcc);
        __syncthreads();
        #pragma unroll
        for (int k = 0; k < 8; k++) {
            float ar[8], br[8];
            *(float4*)(ar)     = *(float4*)&As[k][ty*8];
            *(float4*)(ar + 4) = *(float4*)&As[k][ty*8 + 4];
            *(float4*)(br)     = *(float4*)&Bs[k][tx*8];
            *(float4*)(br + 4) = *(float4*)&Bs[k][tx*8 + 4];
            #pragma unroll
            for (int i = 0; i < 8; i++)
                #pragma unroll
                for (int j = 0; j < 8; j++)
                    acc[i][j] += ar[i] * br[j];
        }
        __syncthreads();
    }

    const float scale = 0.17677669529663687f;  // 32^-0.5
    #pragma unroll
    for (int i = 0; i < 8; i++) {
        int gr = row0 + ty*8 + i;
        int bI = gr >> 6, nI = gr & 63;
        #pragma unroll
        for (int j = 0; j < 8; j++) {
            int gc = col0 + tx*8 + j;
            float v = acc[i][j] + bias[gc];
            if (mode == 0) {
                v *= scale;
                int h = gc >> 5, d = gc & 31;
                g_q[(((size_t)bI*HEADS + h)*NTOK + nI)*HD + d] = v;
            } else if (mode == 1) {
                if (gc < 256) {
                    int h = gc >> 5, d = gc & 31;
                    g_k[(((size_t)bI*HEADS + h)*NTOK + nI)*HD + d] = v;
                } else {
                    int gc2 = gc - 256;
                    int h = gc2 >> 5, d = gc2 & 31;
                    g_v[(((size_t)bI*HEADS + h)*NTOK + nI)*HD + d] = v;
                }
            } else {
                D[(size_t)gr * DIM + gc] = v;
            }
        }
    }
}

// ============================================================
// Kernel 3: fused attention per (window, head)
//   cosine sim, tau, bias, mask, softmax, PV
// ============================================================
__global__ void __launch_bounds__(256) attn_kernel(const float* __restrict__ mask)
{
    __shared__ float qs[NTOK*33];
    __shared__ float ks[NTOK*33];
    __shared__ float vs[NTOK*33];
    __shared__ float Ss[NTOK*65];
    __shared__ float qn[NTOK], kn[NTOK];

    int b = blockIdx.x, h = blockIdx.y;
    int tid = threadIdx.x;
    size_t base = ((size_t)(b*HEADS + h)) * NTOK * HD;

    // cooperative load q,k,v (64x32) into padded smem
    #pragma unroll
    for (int e = tid*4; e < NTOK*HD; e += 1024) {
        float4 tq = *(const float4*)(g_q + base + e);
        float4 tk = *(const float4*)(g_k + base + e);
        float4 tv = *(const float4*)(g_v + base + e);
        int n = e >> 5, d = e & 31, o = n*33 + d;
        qs[o] = tq.x; qs[o+1] = tq.y; qs[o+2] = tq.z; qs[o+3] = tq.w;
        ks[o] = tk.x; ks[o+1] = tk.y; ks[o+2] = tk.z; ks[o+3] = tk.w;
        vs[o] = tv.x; vs[o+1] = tv.y; vs[o+2] = tv.z; vs[o+3] = tv.w;
    }
    __syncthreads();

    // row norms
    if (tid < 64) {
        float s = 0.f;
        #pragma unroll
        for (int k = 0; k < HD; k++) { float t = qs[tid*33 + k]; s += t*t; }
        qn[tid] = sqrtf(s);
    } else if (tid < 128) {
        int i = tid - 64;
        float s = 0.f;
        #pragma unroll
        for (int k = 0; k < HD; k++) { float t = ks[i*33 + k]; s += t*t; }
        kn[i] = sqrtf(s);
    }
    __syncthreads();

    int i = tid & 63;
    int g = tid >> 6;          // 4 groups of 16 cols

    // S = q @ k^T (each thread: one row i, 16 cols)
    float qr[HD];
    #pragma unroll
    for (int k = 0; k < HD; k++) qr[k] = qs[i*33 + k];
    float acc[16];
    #pragma unroll
    for (int jj = 0; jj < 16; jj++) acc[jj] = 0.f;
    #pragma unroll
    for (int k = 0; k < HD; k++) {
        float qv = qr[k];
        #pragma unroll
        for (int jj = 0; jj < 16; jj++)
            acc[jj] += qv * ks[(g*16 + jj)*33 + k];
    }

    // cosine normalize + tau + bias + mask
    {
        float qni = qn[i];
        int w = b & (NW - 1);
        int ij = i*64 + g*16;
        const float* bp2 = g_bias   + h*NTOK*NTOK + ij;
        const float* itp = g_invtau + h*NTOK*NTOK + ij;
        const float* mp  = mask + (size_t)w*NTOK*NTOK + ij;
        #pragma unroll
        for (int jj = 0; jj < 16; jj++) {
            int j = g*16 + jj;
            float denom = fmaxf(qni * kn[j], 1e-6f);
            Ss[i*65 + j] = __fdividef(acc[jj], denom) * itp[jj] + bp2[jj] + mp[jj];
        }
    }
    __syncthreads();

    // softmax: 8 warps x 8 rows
    {
        int lane = tid & 31, warp = tid >> 5;
        for (int r = warp*8; r < warp*8 + 8; r++) {
            float s0 = Ss[r*65 + lane], s1 = Ss[r*65 + lane + 32];
            float m = fmaxf(s0, s1);
            #pragma unroll
            for (int off = 16; off > 0; off >>= 1)
                m = fmaxf(m, __shfl_xor_sync(0xffffffffu, m, off));
            float e0 = __expf(s0 - m), e1 = __expf(s1 - m);
            float sm = e0 + e1;
            #pragma unroll
            for (int off = 16; off > 0; off >>= 1)
                sm += __shfl_xor_sync(0xffffffffu, sm, off);
            float inv = __fdividef(1.f, sm);
            Ss[r*65 + lane]      = e0 * inv;
            Ss[r*65 + lane + 32] = e1 * inv;
        }
    }
    __syncthreads();

    // O = P @ V (each thread: row i, 8 d's)
    {
        int dg = g;
        float pr[64];
        #pragma unroll
        for (int j = 0; j < 64; j++) pr[j] = Ss[i*65 + j];
        float o8[8];
        #pragma unroll
        for (int dd = 0; dd < 8; dd++) o8[dd] = 0.f;
        #pragma unroll
        for (int j = 0; j < 64; j++) {
            float p = pr[j];
            #pragma unroll
            for (int dd = 0; dd < 8; dd++)
                o8[dd] += p * vs[j*33 + dg*8 + dd];
        }
        float* op = g_ao + ((size_t)b*NTOK + i)*DIM + h*HD + dg*8;
        *(float4*)(op)     = make_float4(o8[0], o8[1], o8[2], o8[3]);
        *(float4*)(op + 4) = make_float4(o8[4], o8[5], o8[6], o8[7]);
    }
}

// ============================================================
// launch
// ============================================================
extern "C" void kernel_launch(void* const* d_in, const int* in_sizes, int n_in,
                              void* d_out, int out_size)
{
    const float* x      = (const float*)d_in[0];
    const float* KV     = (const float*)d_in[1];
    const float* mask   = (const float*)d_in[2];
    const float* Wq     = (const float*)d_in[3];
    const float* bq     = (const float*)d_in[4];
    const float* Wkv    = (const float*)d_in[5];
    const float* bkv    = (const float*)d_in[6];
    const float* Wp     = (const float*)d_in[7];
    const float* bp     = (const float*)d_in[8];
    const float* cpb_w1 = (const float*)d_in[9];
    const float* cpb_b1 = (const float*)d_in[10];
    const float* cpb_w2 = (const float*)d_in[11];
    const float* cpb_b2 = (const float*)d_in[12];
    const float* tau    = (const float*)d_in[13];
    const float* lri    = (const float*)d_in[14];
    float* out = (float*)d_out;

    const int MROWS = BWIN * NTOK;       // 131072
    const int MT = MROWS / 128;          // 1024

    bias_kernel<<<(NTOK*NTOK + 255)/256, 256>>>(cpb_w1, cpb_b1, cpb_w2, cpb_b2, tau, lri);
    sgemm_kernel<<<dim3(2, MT), 256>>>(x,  Wq,  bq,  nullptr, 256, 0);
    sgemm_kernel<<<dim3(4, MT), 256>>>(KV, Wkv, bkv, nullptr, 512, 1);
    attn_kernel<<<dim3(BWIN, HEADS), 256>>>(mask);
    sgemm_kernel<<<dim3(2, MT), 256>>>(nullptr, Wp, bp, out, 256, 2);
}

// round 2
// speedup vs baseline: 1.7222x; 1.7222x over previous
#include <cuda_runtime.h>
#include <cuda_bf16.h>
#include <cstdint>

#define BWIN 2048
#define NTOK 64
#define DIM  256
#define HEADS 8
#define HD   32
#define NW   64

// ---- scratch (device globals; no allocations allowed) ----
__device__ float g_q [BWIN*HEADS*NTOK*HD];   // (b,h,n,d)
__device__ float g_k [BWIN*HEADS*NTOK*HD];
__device__ float g_v [BWIN*HEADS*NTOK*HD];
__device__ float g_ao[BWIN*NTOK*DIM];        // (b,n,c) attention output
__device__ float g_bias  [HEADS*NTOK*NTOK];  // (h,i,j) CPB bias
__device__ float g_invtau[HEADS*NTOK*NTOK];  // 1/max(tau,0.01)

// ============================================================
// Kernel 1: precompute CPB bias MLP + inv-tau tables
// ============================================================
__global__ void bias_kernel(const float* __restrict__ w1, const float* __restrict__ b1,
                            const float* __restrict__ w2, const float* __restrict__ b2,
                            const float* __restrict__ tau, const float* __restrict__ lri)
{
    int idx = blockIdx.x * blockDim.x + threadIdx.x;
    if (idx >= NTOK*NTOK) return;
    float r0 = lri[idx*2 + 0];
    float r1 = lri[idx*2 + 1];
    float acc[HEADS];
    #pragma unroll
    for (int h = 0; h < HEADS; h++) acc[h] = 0.f;
    for (int k = 0; k < 256; k++) {
        float hk = fmaxf(r0 * w1[k] + r1 * w1[256 + k] + b1[k], 0.f);
        #pragma unroll
        for (int h = 0; h < HEADS; h++) acc[h] += hk * w2[k*HEADS + h];
    }
    #pragma unroll
    for (int h = 0; h < HEADS; h++) {
        g_bias[h*NTOK*NTOK + idx] = acc[h] + b2[h];
        g_invtau[h*NTOK*NTOK + idx] = 1.0f / fmaxf(tau[h*NTOK*NTOK + idx], 0.01f);
    }
}

// ============================================================
// Tensor-core GEMM: bf16 split (Ah+Al)(Bh+Bl), drop Al*Bl.
// C = A[M,K=256] @ B[256,ldb] tile 128x128, 8 warps (4m x 2n),
// warp tile 32x64 via m16n8k16.
// ============================================================

__device__ __forceinline__ void mma16816(float* c, const uint32_t* a, const uint32_t* b) {
    asm volatile("mma.sync.aligned.m16n8k16.row.col.f32.bf16.bf16.f32 "
        "{%0,%1,%2,%3}, {%4,%5,%6,%7}, {%8,%9}, {%0,%1,%2,%3};\n"
        : "+f"(c[0]), "+f"(c[1]), "+f"(c[2]), "+f"(c[3])
        : "r"(a[0]), "r"(a[1]), "r"(a[2]), "r"(a[3]), "r"(b[0]), "r"(b[1]));
}
__device__ __forceinline__ void ldsm_x4(uint32_t* r, uint32_t addr) {
    asm volatile("ldmatrix.sync.aligned.m8n8.x4.shared.b16 {%0,%1,%2,%3}, [%4];"
        : "=r"(r[0]), "=r"(r[1]), "=r"(r[2]), "=r"(r[3]) : "r"(addr));
}
__device__ __forceinline__ void ldsm_x2t(uint32_t* r, uint32_t addr) {
    asm volatile("ldmatrix.sync.aligned.m8n8.x2.trans.shared.b16 {%0,%1}, [%2];"
        : "=r"(r[0]), "=r"(r[1]) : "r"(addr));
}

__device__ __forceinline__ uint32_t pack_hi(float a, float b, float& ra, float& rb) {
    __nv_bfloat16 ha = __float2bfloat16_rn(a);
    __nv_bfloat16 hb = __float2bfloat16_rn(b);
    ra = a - __bfloat162float(ha);
    rb = b - __bfloat162float(hb);
    return ((uint32_t)__bfloat16_as_ushort(hb) << 16) | (uint32_t)__bfloat16_as_ushort(ha);
}
__device__ __forceinline__ uint32_t pack2(float a, float b) {
    return ((uint32_t)__bfloat16_as_ushort(__float2bfloat16_rn(b)) << 16)
         | (uint32_t)__bfloat16_as_ushort(__float2bfloat16_rn(a));
}

__device__ __forceinline__ void store_pair(int mode, int r, int c, float v0, float v1,
                                           const float* __restrict__ bias,
                                           float* __restrict__ D)
{
    v0 += bias[c]; v1 += bias[c + 1];
    int bI = r >> 6, nI = r & 63;
    if (mode == 0) {
        const float scale = 0.17677669529663687f;
        int h = c >> 5, d = c & 31;
        *(float2*)&g_q[(((size_t)bI*HEADS + h)*NTOK + nI)*HD + d] =
            make_float2(v0*scale, v1*scale);
    } else if (mode == 1) {
        if (c < 256) {
            int h = c >> 5, d = c & 31;
            *(float2*)&g_k[(((size_t)bI*HEADS + h)*NTOK + nI)*HD + d] = make_float2(v0, v1);
        } else {
            int c2 = c - 256;
            int h = c2 >> 5, d = c2 & 31;
            *(float2*)&g_v[(((size_t)bI*HEADS + h)*NTOK + nI)*HD + d] = make_float2(v0, v1);
        }
    } else {
        *(float2*)&D[(size_t)r*DIM + c] = make_float2(v0, v1);
    }
}

__global__ void __launch_bounds__(256) mma_gemm_kernel(
    const float* __restrict__ A, const float* __restrict__ Bm,
    const float* __restrict__ bias, float* __restrict__ D,
    int ldb, int mode)
{
    // A tile: 128 rows x 16 k (bf16), row = 32B, swizzled per 16B half
    // B tile: 16 k-rows x 128 n (bf16), row = 256B, 16B units swizzled by k
    __shared__ alignas(16) char As_h[4096];
    __shared__ alignas(16) char As_l[4096];
    __shared__ alignas(16) char Bs_h[4096];
    __shared__ alignas(16) char Bs_l[4096];

    const float* Ap = (mode == 2) ? g_ao : A;
    int tid = threadIdx.x;
    int lane = tid & 31, wid = tid >> 5;
    int warp_m = wid >> 1, warp_n = wid & 1;
    int row0 = blockIdx.y * 128;
    int col0 = blockIdx.x * 128;

    // gmem load roles
    int m_a = tid >> 2;           // 0..63 (+64 second pass)
    int c_a = tid & 3;            // k-quad within chunk
    int k_b = wid;                // 0..7 (+8 second pass)
    int n_b = lane * 4;           // 0..124

    float acc[2][8][4];
    #pragma unroll
    for (int mt = 0; mt < 2; mt++)
        #pragma unroll
        for (int nt = 0; nt < 8; nt++)
            #pragma unroll
            for (int i = 0; i < 4; i++) acc[mt][nt][i] = 0.f;

    // ldmatrix lane addresses (constant across chunks)
    uint32_t aaddr_h[2], aaddr_l[2];
    {
        int lrow_loc = ((lane >> 3) & 1) * 8 + (lane & 7);
        int lkh = lane >> 4;
        #pragma unroll
        for (int mt = 0; mt < 2; mt++) {
            int m = warp_m * 32 + mt * 16 + lrow_loc;
            uint32_t off = (uint32_t)m * 32u + (uint32_t)((lkh ^ ((m >> 2) & 1)) << 4);
            aaddr_h[mt] = (uint32_t)__cvta_generic_to_shared(As_h + off);
            aaddr_l[mt] = (uint32_t)__cvta_generic_to_shared(As_l + off);
        }
    }
    int bk_lane = (lane & 7) + ((lane >> 3) & 1) * 8;  // lanes 0-15 meaningful
    if (lane >= 16) bk_lane = lane & 15;
    uint32_t bbase_h = (uint32_t)__cvta_generic_to_shared(Bs_h) + (uint32_t)bk_lane * 256u;
    uint32_t bbase_l = (uint32_t)__cvta_generic_to_shared(Bs_l) + (uint32_t)bk_lane * 256u;
    int bkm = bk_lane & 7;

    // prefetch chunk 0
    float4 a0f, a1f, b0f, b1f;
    a0f = *(const float4*)(Ap + (size_t)(row0 + m_a)      * DIM + 4*c_a);
    a1f = *(const float4*)(Ap + (size_t)(row0 + m_a + 64) * DIM + 4*c_a);
    b0f = *(const float4*)(Bm + (size_t)(k_b)     * ldb + col0 + n_b);
    b1f = *(const float4*)(Bm + (size_t)(k_b + 8) * ldb + col0 + n_b);

    // smem store offsets (constant)
    int kh_a = c_a >> 1;
    uint32_t offA0 = (uint32_t)m_a*32u        + (uint32_t)((kh_a ^ ((m_a >> 2) & 1)) << 4)        + (uint32_t)(c_a & 1) * 8u;
    uint32_t offA1 = (uint32_t)(m_a+64)*32u   + (uint32_t)((kh_a ^ (((m_a+64) >> 2) & 1)) << 4)   + (uint32_t)(c_a & 1) * 8u;
    int nu = n_b >> 3;
    uint32_t offB0 = (uint32_t)k_b*256u     + (uint32_t)((nu ^ (k_b & 7)) << 4)     + (uint32_t)(n_b & 7) * 2u;
    uint32_t offB1 = (uint32_t)(k_b+8)*256u + (uint32_t)((nu ^ ((k_b+8) & 7)) << 4) + (uint32_t)(n_b & 7) * 2u;

    for (int kc = 0; kc < DIM/16; kc++) {
        // convert + store current chunk
        {
            float r0, r1, r2, r3;
            uint32_t h0 = pack_hi(a0f.x, a0f.y, r0, r1);
            uint32_t h1 = pack_hi(a0f.z, a0f.w, r2, r3);
            *(uint2*)(As_h + offA0) = make_uint2(h0, h1);
            *(uint2*)(As_l + offA0) = make_uint2(pack2(r0, r1), pack2(r2, r3));
            h0 = pack_hi(a1f.x, a1f.y, r0, r1);
            h1 = pack_hi(a1f.z, a1f.w, r2, r3);
            *(uint2*)(As_h + offA1) = make_uint2(h0, h1);
            *(uint2*)(As_l + offA1) = make_uint2(pack2(r0, r1), pack2(r2, r3));
            h0 = pack_hi(b0f.x, b0f.y, r0, r1);
            h1 = pack_hi(b0f.z, b0f.w, r2, r3);
            *(uint2*)(Bs_h + offB0) = make_uint2(h0, h1);
            *(uint2*)(Bs_l + offB0) = make_uint2(pack2(r0, r1), pack2(r2, r3));
            h0 = pack_hi(b1f.x, b1f.y, r0, r1);
            h1 = pack_hi(b1f.z, b1f.w, r2, r3);
            *(uint2*)(Bs_h + offB1) = make_uint2(h0, h1);
            *(uint2*)(Bs_l + offB1) = make_uint2(pack2(r0, r1), pack2(r2, r3));
        }
        __syncthreads();

        // prefetch next chunk
        if (kc + 1 < DIM/16) {
            int k0 = (kc + 1) * 16;
            a0f = *(const float4*)(Ap + (size_t)(row0 + m_a)      * DIM + k0 + 4*c_a);
            a1f = *(const float4*)(Ap + (size_t)(row0 + m_a + 64) * DIM + k0 + 4*c_a);
            b0f = *(const float4*)(Bm + (size_t)(k0 + k_b)     * ldb + col0 + n_b);
            b1f = *(const float4*)(Bm + (size_t)(k0 + k_b + 8) * ldb + col0 + n_b);
        }

        // compute
        uint32_t ah[2][4], al[2][4];
        ldsm_x4(ah[0], aaddr_h[0]);
        ldsm_x4(ah[1], aaddr_h[1]);
        ldsm_x4(al[0], aaddr_l[0]);
        ldsm_x4(al[1], aaddr_l[1]);
        #pragma unroll
        for (int nt = 0; nt < 8; nt++) {
            int nuT = warp_n * 8 + nt;
            uint32_t boff = (uint32_t)((nuT ^ bkm) << 4);
            uint32_t bh[2], bl[2];
            ldsm_x2t(bh, bbase_h + boff);
            ldsm_x2t(bl, bbase_l + boff);
            mma16816(acc[0][nt], ah[0], bh);
            mma16816(acc[1][nt], ah[1], bh);
            mma16816(acc[0][nt], ah[0], bl);
            mma16816(acc[1][nt], ah[1], bl);
            mma16816(acc[0][nt], al[0], bh);
            mma16816(acc[1][nt], al[1], bh);
        }
        __syncthreads();
    }

    // epilogue
    #pragma unroll
    for (int mt = 0; mt < 2; mt++) {
        int r_base = row0 + warp_m*32 + mt*16 + (lane >> 2);
        #pragma unroll
        for (int nt = 0; nt < 8; nt++) {
            int c_base = col0 + warp_n*64 + nt*8 + 2*(lane & 3);
            store_pair(mode, r_base,     c_base, acc[mt][nt][0], acc[mt][nt][1], bias, D);
            store_pair(mode, r_base + 8, c_base, acc[mt][nt][2], acc[mt][nt][3], bias, D);
        }
    }
}

// ============================================================
// Kernel 3: fused attention per (window, head)
// ============================================================
__global__ void __launch_bounds__(256) attn_kernel(const float* __restrict__ mask)
{
    __shared__ float qs[NTOK*33];
    __shared__ float ks[NTOK*33];
    __shared__ float vs[NTOK*33];
    __shared__ float Ss[NTOK*65];
    __shared__ float qn[NTOK], kn[NTOK];

    int b = blockIdx.x, h = blockIdx.y;
    int tid = threadIdx.x;
    size_t base = ((size_t)(b*HEADS + h)) * NTOK * HD;

    #pragma unroll
    for (int e = tid*4; e < NTOK*HD; e += 1024) {
        float4 tq = *(const float4*)(g_q + base + e);
        float4 tk = *(const float4*)(g_k + base + e);
        float4 tv = *(const float4*)(g_v + base + e);
        int n = e >> 5, d = e & 31, o = n*33 + d;
        qs[o] = tq.x; qs[o+1] = tq.y; qs[o+2] = tq.z; qs[o+3] = tq.w;
        ks[o] = tk.x; ks[o+1] = tk.y; ks[o+2] = tk.z; ks[o+3] = tk.w;
        vs[o] = tv.x; vs[o+1] = tv.y; vs[o+2] = tv.z; vs[o+3] = tv.w;
    }
    __syncthreads();

    if (tid < 64) {
        float s = 0.f;
        #pragma unroll
        for (int k = 0; k < HD; k++) { float t = qs[tid*33 + k]; s += t*t; }
        qn[tid] = sqrtf(s);
    } else if (tid < 128) {
        int i = tid - 64;
        float s = 0.f;
        #pragma unroll
        for (int k = 0; k < HD; k++) { float t = ks[i*33 + k]; s += t*t; }
        kn[i] = sqrtf(s);
    }
    __syncthreads();

    int i = tid & 63;
    int g = tid >> 6;

    float qr[HD];
    #pragma unroll
    for (int k = 0; k < HD; k++) qr[k] = qs[i*33 + k];
    float acc[16];
    #pragma unroll
    for (int jj = 0; jj < 16; jj++) acc[jj] = 0.f;
    #pragma unroll
    for (int k = 0; k < HD; k++) {
        float qv = qr[k];
        #pragma unroll
        for (int jj = 0; jj < 16; jj++)
            acc[jj] += qv * ks[(g*16 + jj)*33 + k];
    }

    {
        float qni = qn[i];
        int w = b & (NW - 1);
        int ij = i*64 + g*16;
        const float* bp2 = g_bias   + h*NTOK*NTOK + ij;
        const float* itp = g_invtau + h*NTOK*NTOK + ij;
        const float* mp  = mask + (size_t)w*NTOK*NTOK + ij;
        #pragma unroll
        for (int jj = 0; jj < 16; jj++) {
            int j = g*16 + jj;
            float denom = fmaxf(qni * kn[j], 1e-6f);
            Ss[i*65 + j] = __fdividef(acc[jj], denom) * itp[jj] + bp2[jj] + mp[jj];
        }
    }
    __syncthreads();

    {
        int lane = tid & 31, warp = tid >> 5;
        for (int r = warp*8; r < warp*8 + 8; r++) {
            float s0 = Ss[r*65 + lane], s1 = Ss[r*65 + lane + 32];
            float m = fmaxf(s0, s1);
            #pragma unroll
            for (int off = 16; off > 0; off >>= 1)
                m = fmaxf(m, __shfl_xor_sync(0xffffffffu, m, off));
            float e0 = __expf(s0 - m), e1 = __expf(s1 - m);
            float sm = e0 + e1;
            #pragma unroll
            for (int off = 16; off > 0; off >>= 1)
                sm += __shfl_xor_sync(0xffffffffu, sm, off);
            float inv = __fdividef(1.f, sm);
            Ss[r*65 + lane]      = e0 * inv;
            Ss[r*65 + lane + 32] = e1 * inv;
        }
    }
    __syncthreads();

    {
        int dg = g;
        float pr[64];
        #pragma unroll
        for (int j = 0; j < 64; j++) pr[j] = Ss[i*65 + j];
        float o8[8];
        #pragma unroll
        for (int dd = 0; dd < 8; dd++) o8[dd] = 0.f;
        #pragma unroll
        for (int j = 0; j < 64; j++) {
            float p = pr[j];
            #pragma unroll
            for (int dd = 0; dd < 8; dd++)
                o8[dd] += p * vs[j*33 + dg*8 + dd];
        }
        float* op = g_ao + ((size_t)b*NTOK + i)*DIM + h*HD + dg*8;
        *(float4*)(op)     = make_float4(o8[0], o8[1], o8[2], o8[3]);
        *(float4*)(op + 4) = make_float4(o8[4], o8[5], o8[6], o8[7]);
    }
}

// ============================================================
// launch
// ============================================================
extern "C" void kernel_launch(void* const* d_in, const int* in_sizes, int n_in,
                              void* d_out, int out_size)
{
    const float* x      = (const float*)d_in[0];
    const float* KV     = (const float*)d_in[1];
    const float* mask   = (const float*)d_in[2];
    const float* Wq     = (const float*)d_in[3];
    const float* bq     = (const float*)d_in[4];
    const float* Wkv    = (const float*)d_in[5];
    const float* bkv    = (const float*)d_in[6];
    const float* Wp     = (const float*)d_in[7];
    const float* bp     = (const float*)d_in[8];
    const float* cpb_w1 = (const float*)d_in[9];
    const float* cpb_b1 = (const float*)d_in[10];
    const float* cpb_w2 = (const float*)d_in[11];
    const float* cpb_b2 = (const float*)d_in[12];
    const float* tau    = (const float*)d_in[13];
    const float* lri    = (const float*)d_in[14];
    float* out = (float*)d_out;

    const int MROWS = BWIN * NTOK;       // 131072
    const int MT = MROWS / 128;          // 1024

    bias_kernel<<<(NTOK*NTOK + 255)/256, 256>>>(cpb_w1, cpb_b1, cpb_w2, cpb_b2, tau, lri);
    mma_gemm_kernel<<<dim3(2, MT), 256>>>(x,  Wq,  bq,  nullptr, 256, 0);
    mma_gemm_kernel<<<dim3(4, MT), 256>>>(KV, Wkv, bkv, nullptr, 512, 1);
    attn_kernel<<<dim3(BWIN, HEADS), 256>>>(mask);
    mma_gemm_kernel<<<dim3(2, MT), 256>>>(nullptr, Wp, bp, out, 256, 2);
}

// round 3
// speedup vs baseline: 2.2752x; 1.3211x over previous
#include <cuda_runtime.h>
#include <cuda_bf16.h>
#include <cstdint>

#define BWIN 2048
#define NTOK 64
#define DIM  256
#define HEADS 8
#define HD   32
#define NW   64

// ---- scratch (device globals; no allocations allowed) ----
__device__ float g_q [BWIN*HEADS*NTOK*HD];   // (b,h,n,d)
__device__ float g_k [BWIN*HEADS*NTOK*HD];
__device__ float g_v [BWIN*HEADS*NTOK*HD];
__device__ float g_ao[BWIN*NTOK*DIM];        // (b,n,c) attention output
__device__ float g_bias  [HEADS*NTOK*NTOK];  // (h,i,j) CPB bias
__device__ float g_invtau[HEADS*NTOK*NTOK];  // 1/max(tau,0.01)

// ============================================================
// Kernel 1: precompute CPB bias MLP + inv-tau tables
// ============================================================
__global__ void bias_kernel(const float* __restrict__ w1, const float* __restrict__ b1,
                            const float* __restrict__ w2, const float* __restrict__ b2,
                            const float* __restrict__ tau, const float* __restrict__ lri)
{
    int idx = blockIdx.x * blockDim.x + threadIdx.x;
    if (idx >= NTOK*NTOK) return;
    float r0 = lri[idx*2 + 0];
    float r1 = lri[idx*2 + 1];
    float acc[HEADS];
    #pragma unroll
    for (int h = 0; h < HEADS; h++) acc[h] = 0.f;
    for (int k = 0; k < 256; k++) {
        float hk = fmaxf(r0 * w1[k] + r1 * w1[256 + k] + b1[k], 0.f);
        #pragma unroll
        for (int h = 0; h < HEADS; h++) acc[h] += hk * w2[k*HEADS + h];
    }
    #pragma unroll
    for (int h = 0; h < HEADS; h++) {
        g_bias[h*NTOK*NTOK + idx] = acc[h] + b2[h];
        g_invtau[h*NTOK*NTOK + idx] = 1.0f / fmaxf(tau[h*NTOK*NTOK + idx], 0.01f);
    }
}

// ============================================================
// Tensor-core GEMM (unchanged from R2): bf16 split, 128x128 tile
// ============================================================
__device__ __forceinline__ void mma16816(float* c, const uint32_t* a, const uint32_t* b) {
    asm volatile("mma.sync.aligned.m16n8k16.row.col.f32.bf16.bf16.f32 "
        "{%0,%1,%2,%3}, {%4,%5,%6,%7}, {%8,%9}, {%0,%1,%2,%3};\n"
        : "+f"(c[0]), "+f"(c[1]), "+f"(c[2]), "+f"(c[3])
        : "r"(a[0]), "r"(a[1]), "r"(a[2]), "r"(a[3]), "r"(b[0]), "r"(b[1]));
}
__device__ __forceinline__ void ldsm_x4(uint32_t* r, uint32_t addr) {
    asm volatile("ldmatrix.sync.aligned.m8n8.x4.shared.b16 {%0,%1,%2,%3}, [%4];"
        : "=r"(r[0]), "=r"(r[1]), "=r"(r[2]), "=r"(r[3]) : "r"(addr));
}
__device__ __forceinline__ void ldsm_x2t(uint32_t* r, uint32_t addr) {
    asm volatile("ldmatrix.sync.aligned.m8n8.x2.trans.shared.b16 {%0,%1}, [%2];"
        : "=r"(r[0]), "=r"(r[1]) : "r"(addr));
}
__device__ __forceinline__ uint32_t pack_hi(float a, float b, float& ra, float& rb) {
    __nv_bfloat16 ha = __float2bfloat16_rn(a);
    __nv_bfloat16 hb = __float2bfloat16_rn(b);
    ra = a - __bfloat162float(ha);
    rb = b - __bfloat162float(hb);
    return ((uint32_t)__bfloat16_as_ushort(hb) << 16) | (uint32_t)__bfloat16_as_ushort(ha);
}
__device__ __forceinline__ uint32_t pack2(float a, float b) {
    return ((uint32_t)__bfloat16_as_ushort(__float2bfloat16_rn(b)) << 16)
         | (uint32_t)__bfloat16_as_ushort(__float2bfloat16_rn(a));
}

__device__ __forceinline__ void store_pair(int mode, int r, int c, float v0, float v1,
                                           const float* __restrict__ bias,
                                           float* __restrict__ D)
{
    v0 += bias[c]; v1 += bias[c + 1];
    int bI = r >> 6, nI = r & 63;
    if (mode == 0) {
        const float scale = 0.17677669529663687f;
        int h = c >> 5, d = c & 31;
        *(float2*)&g_q[(((size_t)bI*HEADS + h)*NTOK + nI)*HD + d] =
            make_float2(v0*scale, v1*scale);
    } else if (mode == 1) {
        if (c < 256) {
            int h = c >> 5, d = c & 31;
            *(float2*)&g_k[(((size_t)bI*HEADS + h)*NTOK + nI)*HD + d] = make_float2(v0, v1);
        } else {
            int c2 = c - 256;
            int h = c2 >> 5, d = c2 & 31;
            *(float2*)&g_v[(((size_t)bI*HEADS + h)*NTOK + nI)*HD + d] = make_float2(v0, v1);
        }
    } else {
        *(float2*)&D[(size_t)r*DIM + c] = make_float2(v0, v1);
    }
}

__global__ void __launch_bounds__(256) mma_gemm_kernel(
    const float* __restrict__ A, const float* __restrict__ Bm,
    const float* __restrict__ bias, float* __restrict__ D,
    int ldb, int mode)
{
    __shared__ alignas(16) char As_h[4096];
    __shared__ alignas(16) char As_l[4096];
    __shared__ alignas(16) char Bs_h[4096];
    __shared__ alignas(16) char Bs_l[4096];

    const float* Ap = (mode == 2) ? g_ao : A;
    int tid = threadIdx.x;
    int lane = tid & 31, wid = tid >> 5;
    int warp_m = wid >> 1, warp_n = wid & 1;
    int row0 = blockIdx.y * 128;
    int col0 = blockIdx.x * 128;

    int m_a = tid >> 2;
    int c_a = tid & 3;
    int k_b = wid;
    int n_b = lane * 4;

    float acc[2][8][4];
    #pragma unroll
    for (int mt = 0; mt < 2; mt++)
        #pragma unroll
        for (int nt = 0; nt < 8; nt++)
            #pragma unroll
            for (int i = 0; i < 4; i++) acc[mt][nt][i] = 0.f;

    uint32_t aaddr_h[2], aaddr_l[2];
    {
        int lrow_loc = ((lane >> 3) & 1) * 8 + (lane & 7);
        int lkh = lane >> 4;
        #pragma unroll
        for (int mt = 0; mt < 2; mt++) {
            int m = warp_m * 32 + mt * 16 + lrow_loc;
            uint32_t off = (uint32_t)m * 32u + (uint32_t)((lkh ^ ((m >> 2) & 1)) << 4);
            aaddr_h[mt] = (uint32_t)__cvta_generic_to_shared(As_h + off);
            aaddr_l[mt] = (uint32_t)__cvta_generic_to_shared(As_l + off);
        }
    }
    int bk_lane = (lane & 7) + ((lane >> 3) & 1) * 8;
    if (lane >= 16) bk_lane = lane & 15;
    uint32_t bbase_h = (uint32_t)__cvta_generic_to_shared(Bs_h) + (uint32_t)bk_lane * 256u;
    uint32_t bbase_l = (uint32_t)__cvta_generic_to_shared(Bs_l) + (uint32_t)bk_lane * 256u;
    int bkm = bk_lane & 7;

    float4 a0f, a1f, b0f, b1f;
    a0f = *(const float4*)(Ap + (size_t)(row0 + m_a)      * DIM + 4*c_a);
    a1f = *(const float4*)(Ap + (size_t)(row0 + m_a + 64) * DIM + 4*c_a);
    b0f = *(const float4*)(Bm + (size_t)(k_b)     * ldb + col0 + n_b);
    b1f = *(const float4*)(Bm + (size_t)(k_b + 8) * ldb + col0 + n_b);

    int kh_a = c_a >> 1;
    uint32_t offA0 = (uint32_t)m_a*32u        + (uint32_t)((kh_a ^ ((m_a >> 2) & 1)) << 4)        + (uint32_t)(c_a & 1) * 8u;
    uint32_t offA1 = (uint32_t)(m_a+64)*32u   + (uint32_t)((kh_a ^ (((m_a+64) >> 2) & 1)) << 4)   + (uint32_t)(c_a & 1) * 8u;
    int nu = n_b >> 3;
    uint32_t offB0 = (uint32_t)k_b*256u     + (uint32_t)((nu ^ (k_b & 7)) << 4)     + (uint32_t)(n_b & 7) * 2u;
    uint32_t offB1 = (uint32_t)(k_b+8)*256u + (uint32_t)((nu ^ ((k_b+8) & 7)) << 4) + (uint32_t)(n_b & 7) * 2u;

    for (int kc = 0; kc < DIM/16; kc++) {
        {
            float r0, r1, r2, r3;
            uint32_t h0 = pack_hi(a0f.x, a0f.y, r0, r1);
            uint32_t h1 = pack_hi(a0f.z, a0f.w, r2, r3);
            *(uint2*)(As_h + offA0) = make_uint2(h0, h1);
            *(uint2*)(As_l + offA0) = make_uint2(pack2(r0, r1), pack2(r2, r3));
            h0 = pack_hi(a1f.x, a1f.y, r0, r1);
            h1 = pack_hi(a1f.z, a1f.w, r2, r3);
            *(uint2*)(As_h + offA1) = make_uint2(h0, h1);
            *(uint2*)(As_l + offA1) = make_uint2(pack2(r0, r1), pack2(r2, r3));
            h0 = pack_hi(b0f.x, b0f.y, r0, r1);
            h1 = pack_hi(b0f.z, b0f.w, r2, r3);
            *(uint2*)(Bs_h + offB0) = make_uint2(h0, h1);
            *(uint2*)(Bs_l + offB0) = make_uint2(pack2(r0, r1), pack2(r2, r3));
            h0 = pack_hi(b1f.x, b1f.y, r0, r1);
            h1 = pack_hi(b1f.z, b1f.w, r2, r3);
            *(uint2*)(Bs_h + offB1) = make_uint2(h0, h1);
            *(uint2*)(Bs_l + offB1) = make_uint2(pack2(r0, r1), pack2(r2, r3));
        }
        __syncthreads();

        if (kc + 1 < DIM/16) {
            int k0 = (kc + 1) * 16;
            a0f = *(const float4*)(Ap + (size_t)(row0 + m_a)      * DIM + k0 + 4*c_a);
            a1f = *(const float4*)(Ap + (size_t)(row0 + m_a + 64) * DIM + k0 + 4*c_a);
            b0f = *(const float4*)(Bm + (size_t)(k0 + k_b)     * ldb + col0 + n_b);
            b1f = *(const float4*)(Bm + (size_t)(k0 + k_b + 8) * ldb + col0 + n_b);
        }

        uint32_t ah[2][4], al[2][4];
        ldsm_x4(ah[0], aaddr_h[0]);
        ldsm_x4(ah[1], aaddr_h[1]);
        ldsm_x4(al[0], aaddr_l[0]);
        ldsm_x4(al[1], aaddr_l[1]);
        #pragma unroll
        for (int nt = 0; nt < 8; nt++) {
            int nuT = warp_n * 8 + nt;
            uint32_t boff = (uint32_t)((nuT ^ bkm) << 4);
            uint32_t bh[2], bl[2];
            ldsm_x2t(bh, bbase_h + boff);
            ldsm_x2t(bl, bbase_l + boff);
            mma16816(acc[0][nt], ah[0], bh);
            mma16816(acc[1][nt], ah[1], bh);
            mma16816(acc[0][nt], ah[0], bl);
            mma16816(acc[1][nt], ah[1], bl);
            mma16816(acc[0][nt], al[0], bh);
            mma16816(acc[1][nt], al[1], bh);
        }
        __syncthreads();
    }

    #pragma unroll
    for (int mt = 0; mt < 2; mt++) {
        int r_base = row0 + warp_m*32 + mt*16 + (lane >> 2);
        #pragma unroll
        for (int nt = 0; nt < 8; nt++) {
            int c_base = col0 + warp_n*64 + nt*8 + 2*(lane & 3);
            store_pair(mode, r_base,     c_base, acc[mt][nt][0], acc[mt][nt][1], bias, D);
            store_pair(mode, r_base + 8, c_base, acc[mt][nt][2], acc[mt][nt][3], bias, D);
        }
    }
}

// ============================================================
// Kernel 3: fused attention per (window, head) — vectorized LDS
// ============================================================
#define QPAD 36   // row stride (words) for q/k/v: 16B aligned, conflict-free octets
#define SPAD 68   // row stride (words) for S/P

__global__ void __launch_bounds__(256) attn_kernel(const float* __restrict__ mask)
{
    __shared__ alignas(16) float qs[NTOK*QPAD];
    __shared__ alignas(16) float ks[NTOK*QPAD];
    __shared__ alignas(16) float vs[NTOK*QPAD];
    __shared__ alignas(16) float Ss[NTOK*SPAD];
    __shared__ float qn[NTOK], kn[NTOK];

    int b = blockIdx.x, h = blockIdx.y;
    int tid = threadIdx.x;
    size_t base = ((size_t)(b*HEADS + h)) * NTOK * HD;

    // cooperative load q,k,v (64x32 floats each) as float4
    #pragma unroll
    for (int e = tid*4; e < NTOK*HD; e += 1024) {
        float4 tq = *(const float4*)(g_q + base + e);
        float4 tk = *(const float4*)(g_k + base + e);
        float4 tv = *(const float4*)(g_v + base + e);
        int n = e >> 5, d = e & 31, o = n*QPAD + d;
        *(float4*)&qs[o] = tq;
        *(float4*)&ks[o] = tk;
        *(float4*)&vs[o] = tv;
    }
    __syncthreads();

    // row norms (vectorized)
    if (tid < 64) {
        float s = 0.f;
        #pragma unroll
        for (int kq = 0; kq < 8; kq++) {
            float4 t = *(float4*)&qs[tid*QPAD + kq*4];
            s += t.x*t.x + t.y*t.y + t.z*t.z + t.w*t.w;
        }
        qn[tid] = sqrtf(s);
    } else if (tid < 128) {
        int i = tid - 64;
        float s = 0.f;
        #pragma unroll
        for (int kq = 0; kq < 8; kq++) {
            float4 t = *(float4*)&ks[i*QPAD + kq*4];
            s += t.x*t.x + t.y*t.y + t.z*t.z + t.w*t.w;
        }
        kn[i] = sqrtf(s);
    }
    __syncthreads();

    int i = tid & 63;
    int g = tid >> 6;          // 4 groups of 16 cols

    // q row into registers as float4s
    float4 qr4[8];
    #pragma unroll
    for (int kq = 0; kq < 8; kq++) qr4[kq] = *(float4*)&qs[i*QPAD + kq*4];

    // S = q @ k^T : thread = row i, cols [g*16, g*16+16)
    float acc[16];
    #pragma unroll
    for (int jj = 0; jj < 16; jj++) {
        const float* kr = &ks[(g*16 + jj)*QPAD];
        float s = 0.f;
        #pragma unroll
        for (int kq = 0; kq < 8; kq++) {
            float4 k4 = *(const float4*)&kr[kq*4];  // broadcast within warp
            s += qr4[kq].x*k4.x + qr4[kq].y*k4.y + qr4[kq].z*k4.z + qr4[kq].w*k4.w;
        }
        acc[jj] = s;
    }

    // cosine normalize + tau + bias + mask (float4 gmem loads)
    {
        float qni = qn[i];
        int w = b & (NW - 1);
        int ij = i*64 + g*16;
        const float* bp2 = g_bias   + h*NTOK*NTOK + ij;
        const float* itp = g_invtau + h*NTOK*NTOK + ij;
        const float* mp  = mask + (size_t)w*NTOK*NTOK + ij;
        #pragma unroll
        for (int jq = 0; jq < 4; jq++) {
            float4 b4 = *(const float4*)(bp2 + jq*4);
            float4 t4 = *(const float4*)(itp + jq*4);
            float4 m4 = *(const float4*)(mp  + jq*4);
            float4 k4 = *(float4*)&kn[0];   // placeholder; replaced below
            (void)k4;
            int j0 = g*16 + jq*4;
            float d0 = fmaxf(qni * kn[j0+0], 1e-6f);
            float d1 = fmaxf(qni * kn[j0+1], 1e-6f);
            float d2 = fmaxf(qni * kn[j0+2], 1e-6f);
            float d3 = fmaxf(qni * kn[j0+3], 1e-6f);
            float4 r;
            r.x = __fdividef(acc[jq*4+0], d0) * t4.x + b4.x + m4.x;
            r.y = __fdividef(acc[jq*4+1], d1) * t4.y + b4.y + m4.y;
            r.z = __fdividef(acc[jq*4+2], d2) * t4.z + b4.z + m4.z;
            r.w = __fdividef(acc[jq*4+3], d3) * t4.w + b4.w + m4.w;
            *(float4*)&Ss[i*SPAD + j0] = r;
        }
    }
    __syncthreads();

    // softmax: 8 warps x 8 rows
    {
        int lane = tid & 31, warp = tid >> 5;
        #pragma unroll
        for (int r = warp*8; r < warp*8 + 8; r++) {
            float s0 = Ss[r*SPAD + lane], s1 = Ss[r*SPAD + lane + 32];
            float m = fmaxf(s0, s1);
            #pragma unroll
            for (int off = 16; off > 0; off >>= 1)
                m = fmaxf(m, __shfl_xor_sync(0xffffffffu, m, off));
            float e0 = __expf(s0 - m), e1 = __expf(s1 - m);
            float sm = e0 + e1;
            #pragma unroll
            for (int off = 16; off > 0; off >>= 1)
                sm += __shfl_xor_sync(0xffffffffu, sm, off);
            float inv = __fdividef(1.f, sm);
            Ss[r*SPAD + lane]      = e0 * inv;
            Ss[r*SPAD + lane + 32] = e1 * inv;
        }
    }
    __syncthreads();

    // O = P @ V : thread = row i, 8 d's (d block g*8)
    {
        float o0 = 0.f, o1 = 0.f, o2 = 0.f, o3 = 0.f;
        float o4 = 0.f, o5 = 0.f, o6 = 0.f, o7 = 0.f;
        #pragma unroll
        for (int jq = 0; jq < 16; jq++) {
            float4 p4 = *(float4*)&Ss[i*SPAD + jq*4];
            #pragma unroll
            for (int t = 0; t < 4; t++) {
                int j = jq*4 + t;
                float p = (t == 0) ? p4.x : (t == 1) ? p4.y : (t == 2) ? p4.z : p4.w;
                float4 v0 = *(float4*)&vs[j*QPAD + g*8];      // broadcast
                float4 v1 = *(float4*)&vs[j*QPAD + g*8 + 4];  // broadcast
                o0 += p*v0.x; o1 += p*v0.y; o2 += p*v0.z; o3 += p*v0.w;
                o4 += p*v1.x; o5 += p*v1.y; o6 += p*v1.z; o7 += p*v1.w;
            }
        }
        float* op = g_ao + ((size_t)b*NTOK + i)*DIM + h*HD + g*8;
        *(float4*)(op)     = make_float4(o0, o1, o2, o3);
        *(float4*)(op + 4) = make_float4(o4, o5, o6, o7);
    }
}

// ============================================================
// launch
// ============================================================
extern "C" void kernel_launch(void* const* d_in, const int* in_sizes, int n_in,
                              void* d_out, int out_size)
{
    const float* x      = (const float*)d_in[0];
    const float* KV     = (const float*)d_in[1];
    const float* mask   = (const float*)d_in[2];
    const float* Wq     = (const float*)d_in[3];
    const float* bq     = (const float*)d_in[4];
    const float* Wkv    = (const float*)d_in[5];
    const float* bkv    = (const float*)d_in[6];
    const float* Wp     = (const float*)d_in[7];
    const float* bp     = (const float*)d_in[8];
    const float* cpb_w1 = (const float*)d_in[9];
    const float* cpb_b1 = (const float*)d_in[10];
    const float* cpb_w2 = (const float*)d_in[11];
    const float* cpb_b2 = (const float*)d_in[12];
    const float* tau    = (const float*)d_in[13];
    const float* lri    = (const float*)d_in[14];
    float* out = (float*)d_out;

    const int MROWS = BWIN * NTOK;       // 131072
    const int MT = MROWS / 128;          // 1024

    bias_kernel<<<(NTOK*NTOK + 255)/256, 256>>>(cpb_w1, cpb_b1, cpb_w2, cpb_b2, tau, lri);
    mma_gemm_kernel<<<dim3(2, MT), 256>>>(x,  Wq,  bq,  nullptr, 256, 0);
    mma_gemm_kernel<<<dim3(4, MT), 256>>>(KV, Wkv, bkv, nullptr, 512, 1);
    attn_kernel<<<dim3(BWIN, HEADS), 256>>>(mask);
    mma_gemm_kernel<<<dim3(2, MT), 256>>>(nullptr, Wp, bp, out, 256, 2);
}

// round 4
// speedup vs baseline: 3.1976x; 1.4054x over previous
#include <cuda_runtime.h>
#include <cuda_bf16.h>
#include <cstdint>

#define BWIN 2048
#define NTOK 64
#define DIM  256
#define HEADS 8
#define HD   32
#define NW   64

// ---- scratch (device globals; no allocations allowed) ----
__device__ float g_q [BWIN*HEADS*NTOK*HD];   // (b,h,n,d)
__device__ float g_k [BWIN*HEADS*NTOK*HD];
__device__ float g_v [BWIN*HEADS*NTOK*HD];
__device__ float g_ao[BWIN*NTOK*DIM];        // (b,n,c)
__device__ float g_bias  [HEADS*NTOK*NTOK];
__device__ float g_invtau[HEADS*NTOK*NTOK];
// pre-split weights: [Wq | Wkv | Wp] = 65536 + 131072 + 65536
__device__ __nv_bfloat16 g_wbh[262144];
__device__ __nv_bfloat16 g_wbl[262144];

// ============================================================
// helpers
// ============================================================
__device__ __forceinline__ void mma16816(float* c, const uint32_t* a, const uint32_t* b) {
    asm volatile("mma.sync.aligned.m16n8k16.row.col.f32.bf16.bf16.f32 "
        "{%0,%1,%2,%3}, {%4,%5,%6,%7}, {%8,%9}, {%0,%1,%2,%3};\n"
        : "+f"(c[0]), "+f"(c[1]), "+f"(c[2]), "+f"(c[3])
        : "r"(a[0]), "r"(a[1]), "r"(a[2]), "r"(a[3]), "r"(b[0]), "r"(b[1]));
}
__device__ __forceinline__ void ldsm_x4(uint32_t* r, uint32_t addr) {
    asm volatile("ldmatrix.sync.aligned.m8n8.x4.shared.b16 {%0,%1,%2,%3}, [%4];"
        : "=r"(r[0]), "=r"(r[1]), "=r"(r[2]), "=r"(r[3]) : "r"(addr));
}
__device__ __forceinline__ void ldsm_x2(uint32_t* r, uint32_t addr) {
    asm volatile("ldmatrix.sync.aligned.m8n8.x2.shared.b16 {%0,%1}, [%2];"
        : "=r"(r[0]), "=r"(r[1]) : "r"(addr));
}
__device__ __forceinline__ void ldsm_x2t(uint32_t* r, uint32_t addr) {
    asm volatile("ldmatrix.sync.aligned.m8n8.x2.trans.shared.b16 {%0,%1}, [%2];"
        : "=r"(r[0]), "=r"(r[1]) : "r"(addr));
}
__device__ __forceinline__ uint32_t pack_hi(float a, float b, float& ra, float& rb) {
    __nv_bfloat16 ha = __float2bfloat16_rn(a);
    __nv_bfloat16 hb = __float2bfloat16_rn(b);
    ra = a - __bfloat162float(ha);
    rb = b - __bfloat162float(hb);
    return ((uint32_t)__bfloat16_as_ushort(hb) << 16) | (uint32_t)__bfloat16_as_ushort(ha);
}
__device__ __forceinline__ uint32_t pack2(float a, float b) {
    return ((uint32_t)__bfloat16_as_ushort(__float2bfloat16_rn(b)) << 16)
         | (uint32_t)__bfloat16_as_ushort(__float2bfloat16_rn(a));
}

// ============================================================
// Kernel 0: pre-split weights to bf16 h/l
// ============================================================
__global__ void prep_w_kernel(const float* __restrict__ Wq,
                              const float* __restrict__ Wkv,
                              const float* __restrict__ Wp)
{
    int i = blockIdx.x * 256 + threadIdx.x;
    if (i >= 262144) return;
    float f;
    if (i < 65536) f = Wq[i];
    else if (i < 196608) f = Wkv[i - 65536];
    else f = Wp[i - 196608];
    __nv_bfloat16 hh = __float2bfloat16_rn(f);
    g_wbh[i] = hh;
    g_wbl[i] = __float2bfloat16_rn(f - __bfloat162float(hh));
}

// ============================================================
// Kernel 1: CPB bias MLP + inv-tau tables
// ============================================================
__global__ void bias_kernel(const float* __restrict__ w1, const float* __restrict__ b1,
                            const float* __restrict__ w2, const float* __restrict__ b2,
                            const float* __restrict__ tau, const float* __restrict__ lri)
{
    int idx = blockIdx.x * blockDim.x + threadIdx.x;
    if (idx >= NTOK*NTOK) return;
    float r0 = lri[idx*2 + 0];
    float r1 = lri[idx*2 + 1];
    float acc[HEADS];
    #pragma unroll
    for (int h = 0; h < HEADS; h++) acc[h] = 0.f;
    for (int k = 0; k < 256; k++) {
        float hk = fmaxf(r0 * w1[k] + r1 * w1[256 + k] + b1[k], 0.f);
        #pragma unroll
        for (int h = 0; h < HEADS; h++) acc[h] += hk * w2[k*HEADS + h];
    }
    #pragma unroll
    for (int h = 0; h < HEADS; h++) {
        g_bias[h*NTOK*NTOK + idx] = acc[h] + b2[h];
        g_invtau[h*NTOK*NTOK + idx] = 1.0f / fmaxf(tau[h*NTOK*NTOK + idx], 0.01f);
    }
}

// ============================================================
// Kernel 2: projection GEMM (bf16 split, preconverted weights)
// ============================================================
__device__ __forceinline__ void store_pair(int mode, int r, int c, float v0, float v1,
                                           const float* __restrict__ bias,
                                           float* __restrict__ D)
{
    v0 += bias[c]; v1 += bias[c + 1];
    int bI = r >> 6, nI = r & 63;
    if (mode == 0) {
        const float scale = 0.17677669529663687f;
        int h = c >> 5, d = c & 31;
        *(float2*)&g_q[(((size_t)bI*HEADS + h)*NTOK + nI)*HD + d] =
            make_float2(v0*scale, v1*scale);
    } else if (mode == 1) {
        if (c < 256) {
            int h = c >> 5, d = c & 31;
            *(float2*)&g_k[(((size_t)bI*HEADS + h)*NTOK + nI)*HD + d] = make_float2(v0, v1);
        } else {
            int c2 = c - 256;
            int h = c2 >> 5, d = c2 & 31;
            *(float2*)&g_v[(((size_t)bI*HEADS + h)*NTOK + nI)*HD + d] = make_float2(v0, v1);
        }
    } else {
        *(float2*)&D[(size_t)r*DIM + c] = make_float2(v0, v1);
    }
}

__global__ void __launch_bounds__(256) mma_gemm_kernel(
    const float* __restrict__ A,
    const float* __restrict__ bias, float* __restrict__ D,
    int ldb, int mode, int woff)
{
    __shared__ alignas(16) char As_h[4096];
    __shared__ alignas(16) char As_l[4096];
    __shared__ alignas(16) char Bs_h[4096];
    __shared__ alignas(16) char Bs_l[4096];

    const float* Ap = (mode == 2) ? g_ao : A;
    int tid = threadIdx.x;
    int lane = tid & 31, wid = tid >> 5;
    int warp_m = wid >> 1, warp_n = wid & 1;
    int row0 = blockIdx.y * 128;
    int col0 = blockIdx.x * 128;

    int m_a = tid >> 2;
    int c_a = tid & 3;
    int k_b2 = tid >> 4;          // 0..15
    int n_b2 = (tid & 15) * 8;    // 0..120

    float acc[2][8][4];
    #pragma unroll
    for (int mt = 0; mt < 2; mt++)
        #pragma unroll
        for (int nt = 0; nt < 8; nt++)
            #pragma unroll
            for (int i = 0; i < 4; i++) acc[mt][nt][i] = 0.f;

    uint32_t aaddr_h[2], aaddr_l[2];
    {
        int lrow_loc = ((lane >> 3) & 1) * 8 + (lane & 7);
        int lkh = lane >> 4;
        #pragma unroll
        for (int mt = 0; mt < 2; mt++) {
            int m = warp_m * 32 + mt * 16 + lrow_loc;
            uint32_t off = (uint32_t)m * 32u + (uint32_t)((lkh ^ ((m >> 2) & 1)) << 4);
            aaddr_h[mt] = (uint32_t)__cvta_generic_to_shared(As_h + off);
            aaddr_l[mt] = (uint32_t)__cvta_generic_to_shared(As_l + off);
        }
    }
    int bk_lane = lane & 15;
    uint32_t bbase_h = (uint32_t)__cvta_generic_to_shared(Bs_h) + (uint32_t)bk_lane * 256u;
    uint32_t bbase_l = (uint32_t)__cvta_generic_to_shared(Bs_l) + (uint32_t)bk_lane * 256u;
    int bkm = bk_lane & 7;

    const __nv_bfloat16* Bh = g_wbh + woff;
    const __nv_bfloat16* Bl = g_wbl + woff;

    float4 a0f, a1f;
    uint4 b_h, b_l;
    a0f = *(const float4*)(Ap + (size_t)(row0 + m_a)      * DIM + 4*c_a);
    a1f = *(const float4*)(Ap + (size_t)(row0 + m_a + 64) * DIM + 4*c_a);
    b_h = *(const uint4*)(Bh + (size_t)k_b2 * ldb + col0 + n_b2);
    b_l = *(const uint4*)(Bl + (size_t)k_b2 * ldb + col0 + n_b2);

    int kh_a = c_a >> 1;
    uint32_t offA0 = (uint32_t)m_a*32u        + (uint32_t)((kh_a ^ ((m_a >> 2) & 1)) << 4)        + (uint32_t)(c_a & 1) * 8u;
    uint32_t offA1 = (uint32_t)(m_a+64)*32u   + (uint32_t)((kh_a ^ (((m_a+64) >> 2) & 1)) << 4)   + (uint32_t)(c_a & 1) * 8u;
    uint32_t offB  = (uint32_t)k_b2*256u + (uint32_t)(((n_b2 >> 3) ^ (k_b2 & 7)) << 4);

    for (int kc = 0; kc < DIM/16; kc++) {
        {
            float r0, r1, r2, r3;
            uint32_t h0 = pack_hi(a0f.x, a0f.y, r0, r1);
            uint32_t h1 = pack_hi(a0f.z, a0f.w, r2, r3);
            *(uint2*)(As_h + offA0) = make_uint2(h0, h1);
            *(uint2*)(As_l + offA0) = make_uint2(pack2(r0, r1), pack2(r2, r3));
            h0 = pack_hi(a1f.x, a1f.y, r0, r1);
            h1 = pack_hi(a1f.z, a1f.w, r2, r3);
            *(uint2*)(As_h + offA1) = make_uint2(h0, h1);
            *(uint2*)(As_l + offA1) = make_uint2(pack2(r0, r1), pack2(r2, r3));
            *(uint4*)(Bs_h + offB) = b_h;
            *(uint4*)(Bs_l + offB) = b_l;
        }
        __syncthreads();

        if (kc + 1 < DIM/16) {
            int k0 = (kc + 1) * 16;
            a0f = *(const float4*)(Ap + (size_t)(row0 + m_a)      * DIM + k0 + 4*c_a);
            a1f = *(const float4*)(Ap + (size_t)(row0 + m_a + 64) * DIM + k0 + 4*c_a);
            b_h = *(const uint4*)(Bh + (size_t)(k0 + k_b2) * ldb + col0 + n_b2);
            b_l = *(const uint4*)(Bl + (size_t)(k0 + k_b2) * ldb + col0 + n_b2);
        }

        uint32_t ah[2][4], al[2][4];
        ldsm_x4(ah[0], aaddr_h[0]);
        ldsm_x4(ah[1], aaddr_h[1]);
        ldsm_x4(al[0], aaddr_l[0]);
        ldsm_x4(al[1], aaddr_l[1]);
        #pragma unroll
        for (int nt = 0; nt < 8; nt++) {
            int nuT = warp_n * 8 + nt;
            uint32_t boff = (uint32_t)((nuT ^ bkm) << 4);
            uint32_t bh2[2], bl2[2];
            ldsm_x2t(bh2, bbase_h + boff);
            ldsm_x2t(bl2, bbase_l + boff);
            mma16816(acc[0][nt], ah[0], bh2);
            mma16816(acc[1][nt], ah[1], bh2);
            mma16816(acc[0][nt], ah[0], bl2);
            mma16816(acc[1][nt], ah[1], bl2);
            mma16816(acc[0][nt], al[0], bh2);
            mma16816(acc[1][nt], al[1], bh2);
        }
        __syncthreads();
    }

    #pragma unroll
    for (int mt = 0; mt < 2; mt++) {
        int r_base = row0 + warp_m*32 + mt*16 + (lane >> 2);
        #pragma unroll
        for (int nt = 0; nt < 8; nt++) {
            int c_base = col0 + warp_n*64 + nt*8 + 2*(lane & 3);
            store_pair(mode, r_base,     c_base, acc[mt][nt][0], acc[mt][nt][1], bias, D);
            store_pair(mode, r_base + 8, c_base, acc[mt][nt][2], acc[mt][nt][3], bias, D);
        }
    }
}

// ============================================================
// Kernel 3: tensor-core attention, 4 warps/CTA, 4 windows/CTA
// smem row layout (q/k/v): 64 rows x 128B; 16B unit u = part*4+ko,
// physical octet = u ^ (row&7)  (conflict-free ldmatrix)
// ============================================================
__device__ __forceinline__ void store_cvt16(char* sm, int r, int d0, const float* f) {
    #pragma unroll
    for (int u = 0; u < 2; u++) {
        int o = u * 8;
        float rr[8];
        uint4 H, L;
        H.x = pack_hi(f[o+0], f[o+1], rr[0], rr[1]);
        H.y = pack_hi(f[o+2], f[o+3], rr[2], rr[3]);
        H.z = pack_hi(f[o+4], f[o+5], rr[4], rr[5]);
        H.w = pack_hi(f[o+6], f[o+7], rr[6], rr[7]);
        L.x = pack2(rr[0], rr[1]);
        L.y = pack2(rr[2], rr[3]);
        L.z = pack2(rr[4], rr[5]);
        L.w = pack2(rr[6], rr[7]);
        int ko = (d0 >> 3) + u;
        *(uint4*)(sm + r*128 + ((ko ^ (r & 7)) << 4))       = H;
        *(uint4*)(sm + r*128 + (((4 + ko) ^ (r & 7)) << 4)) = L;
    }
}

__global__ void __launch_bounds__(128) attn_mma_kernel(const float* __restrict__ mask)
{
    __shared__ alignas(16) char qsm[8192];
    __shared__ alignas(16) char ksm[8192];
    __shared__ alignas(16) char vsm[8192];
    __shared__ float qn_s[NTOK], kn_s[NTOK];

    int gx = blockIdx.x;                 // 0..511
    int h  = blockIdx.y;
    int w  = gx & 63, jg = gx >> 6;
    int tid = threadIdx.x;
    int lane = tid & 31, wid = tid >> 5;
    int mbase = wid * 16;

    uint32_t qsb = (uint32_t)__cvta_generic_to_shared(qsm);
    uint32_t ksb = (uint32_t)__cvta_generic_to_shared(ksm);
    uint32_t vsb = (uint32_t)__cvta_generic_to_shared(vsm);

    const float* itp = g_invtau + h*4096;
    const float* bpp = g_bias   + h*4096;
    const float* mpp = mask + (size_t)w*4096;

    int r_ld = tid >> 1;
    int d0   = (tid & 1) * 16;

    for (int t = 0; t < 4; t++) {
        int b = w + 64 * (jg * 4 + t);
        size_t base = ((size_t)(b*HEADS + h)) * (NTOK*HD);

        // ---- load + convert + norms ----
        {
            float f[16];
            const float* src = g_q + base + r_ld*HD + d0;
            *(float4*)(f)    = *(const float4*)(src);
            *(float4*)(f+4)  = *(const float4*)(src+4);
            *(float4*)(f+8)  = *(const float4*)(src+8);
            *(float4*)(f+12) = *(const float4*)(src+12);
            float ss = 0.f;
            #pragma unroll
            for (int i = 0; i < 16; i++) ss += f[i]*f[i];
            ss += __shfl_xor_sync(0xffffffffu, ss, 1);
            if ((tid & 1) == 0) qn_s[r_ld] = sqrtf(ss);
            store_cvt16(qsm, r_ld, d0, f);

            src = g_k + base + r_ld*HD + d0;
            *(float4*)(f)    = *(const float4*)(src);
            *(float4*)(f+4)  = *(const float4*)(src+4);
            *(float4*)(f+8)  = *(const float4*)(src+8);
            *(float4*)(f+12) = *(const float4*)(src+12);
            ss = 0.f;
            #pragma unroll
            for (int i = 0; i < 16; i++) ss += f[i]*f[i];
            ss += __shfl_xor_sync(0xffffffffu, ss, 1);
            if ((tid & 1) == 0) kn_s[r_ld] = sqrtf(ss);
            store_cvt16(ksm, r_ld, d0, f);

            src = g_v + base + r_ld*HD + d0;
            *(float4*)(f)    = *(const float4*)(src);
            *(float4*)(f+4)  = *(const float4*)(src+4);
            *(float4*)(f+8)  = *(const float4*)(src+8);
            *(float4*)(f+12) = *(const float4*)(src+12);
            store_cvt16(vsm, r_ld, d0, f);
        }
        __syncthreads();

        // ---- S = q k^T ----
        float sf[8][4];
        #pragma unroll
        for (int nt = 0; nt < 8; nt++)
            #pragma unroll
            for (int i = 0; i < 4; i++) sf[nt][i] = 0.f;

        #pragma unroll
        for (int kt = 0; kt < 2; kt++) {
            int lrow = mbase + ((lane >> 3) & 1) * 8 + (lane & 7);
            int ko   = kt*2 + (lane >> 4);
            uint32_t ah[4], al[4];
            ldsm_x4(ah, qsb + lrow*128 + ((ko ^ (lrow & 7)) << 4));
            ldsm_x4(al, qsb + lrow*128 + (((4 + ko) ^ (lrow & 7)) << 4));
            int krow_l = (lane & 7);
            int kko    = kt*2 + ((lane >> 3) & 1);
            #pragma unroll
            for (int nt = 0; nt < 8; nt++) {
                int krow = nt*8 + krow_l;
                uint32_t bh[2], bl[2];
                ldsm_x2(bh, ksb + krow*128 + ((kko ^ (krow & 7)) << 4));
                ldsm_x2(bl, ksb + krow*128 + (((4 + kko) ^ (krow & 7)) << 4));
                mma16816(sf[nt], ah, bh);
                mma16816(sf[nt], ah, bl);
                mma16816(sf[nt], al, bh);
            }
        }

        // ---- epilogue: cosine norm + tau + bias + mask ----
        int rA = mbase + (lane >> 2);
        int rB = rA + 8;
        float qnA = qn_s[rA], qnB = qn_s[rB];
        #pragma unroll
        for (int nt = 0; nt < 8; nt++) {
            int c0 = nt*8 + 2*(lane & 3);
            float2 kn2 = *(float2*)&kn_s[c0];
            int iA = rA*64 + c0, iB = rB*64 + c0;
            float2 tA = *(const float2*)(itp + iA);
            float2 tB = *(const float2*)(itp + iB);
            float2 bA = *(const float2*)(bpp + iA);
            float2 bB = *(const float2*)(bpp + iB);
            float2 mA = *(const float2*)(mpp + iA);
            float2 mB = *(const float2*)(mpp + iB);
            sf[nt][0] = __fdividef(sf[nt][0], fmaxf(qnA*kn2.x, 1e-6f)) * tA.x + bA.x + mA.x;
            sf[nt][1] = __fdividef(sf[nt][1], fmaxf(qnA*kn2.y, 1e-6f)) * tA.y + bA.y + mA.y;
            sf[nt][2] = __fdividef(sf[nt][2], fmaxf(qnB*kn2.x, 1e-6f)) * tB.x + bB.x + mB.x;
            sf[nt][3] = __fdividef(sf[nt][3], fmaxf(qnB*kn2.y, 1e-6f)) * tB.y + bB.y + mB.y;
        }

        // ---- fragment softmax (rows rA, rB) ----
        {
            float mA = -1e30f, mB = -1e30f;
            #pragma unroll
            for (int nt = 0; nt < 8; nt++) {
                mA = fmaxf(mA, fmaxf(sf[nt][0], sf[nt][1]));
                mB = fmaxf(mB, fmaxf(sf[nt][2], sf[nt][3]));
            }
            mA = fmaxf(mA, __shfl_xor_sync(0xffffffffu, mA, 1));
            mA = fmaxf(mA, __shfl_xor_sync(0xffffffffu, mA, 2));
            mB = fmaxf(mB, __shfl_xor_sync(0xffffffffu, mB, 1));
            mB = fmaxf(mB, __shfl_xor_sync(0xffffffffu, mB, 2));
            float sA = 0.f, sB = 0.f;
            #pragma unroll
            for (int nt = 0; nt < 8; nt++) {
                sf[nt][0] = __expf(sf[nt][0] - mA); sA += sf[nt][0];
                sf[nt][1] = __expf(sf[nt][1] - mA); sA += sf[nt][1];
                sf[nt][2] = __expf(sf[nt][2] - mB); sB += sf[nt][2];
                sf[nt][3] = __expf(sf[nt][3] - mB); sB += sf[nt][3];
            }
            sA += __shfl_xor_sync(0xffffffffu, sA, 1);
            sA += __shfl_xor_sync(0xffffffffu, sA, 2);
            sB += __shfl_xor_sync(0xffffffffu, sB, 1);
            sB += __shfl_xor_sync(0xffffffffu, sB, 2);
            float iA2 = __fdividef(1.f, sA);
            float iB2 = __fdividef(1.f, sB);
            #pragma unroll
            for (int nt = 0; nt < 8; nt++) {
                sf[nt][0] *= iA2; sf[nt][1] *= iA2;
                sf[nt][2] *= iB2; sf[nt][3] *= iB2;
            }
        }

        // ---- O = P V ----
        float of[4][4];
        #pragma unroll
        for (int nt = 0; nt < 4; nt++)
            #pragma unroll
            for (int i = 0; i < 4; i++) of[nt][i] = 0.f;

        #pragma unroll
        for (int kt2 = 0; kt2 < 4; kt2++) {
            int ntA = 2*kt2, ntB = 2*kt2 + 1;
            uint32_t pah[4], pal[4];
            float r0, r1;
            pah[0] = pack_hi(sf[ntA][0], sf[ntA][1], r0, r1); pal[0] = pack2(r0, r1);
            pah[1] = pack_hi(sf[ntA][2], sf[ntA][3], r0, r1); pal[1] = pack2(r0, r1);
            pah[2] = pack_hi(sf[ntB][0], sf[ntB][1], r0, r1); pal[2] = pack2(r0, r1);
            pah[3] = pack_hi(sf[ntB][2], sf[ntB][3], r0, r1); pal[3] = pack2(r0, r1);
            int vrow = kt2*16 + (lane & 15);
            int vsw = vrow & 7;
            #pragma unroll
            for (int nt2 = 0; nt2 < 4; nt2++) {
                uint32_t bh[2], bl[2];
                ldsm_x2t(bh, vsb + vrow*128 + ((nt2 ^ vsw) << 4));
                ldsm_x2t(bl, vsb + vrow*128 + (((4 + nt2) ^ vsw) << 4));
                mma16816(of[nt2], pah, bh);
                mma16816(of[nt2], pah, bl);
                mma16816(of[nt2], pal, bh);
            }
        }

        // ---- store O ----
        {
            float* ob = g_ao + ((size_t)b*NTOK)*DIM + h*HD;
            #pragma unroll
            for (int nt2 = 0; nt2 < 4; nt2++) {
                int c = nt2*8 + 2*(lane & 3);
                *(float2*)(ob + (size_t)rA*DIM + c) = make_float2(of[nt2][0], of[nt2][1]);
                *(float2*)(ob + (size_t)rB*DIM + c) = make_float2(of[nt2][2], of[nt2][3]);
            }
        }
        __syncthreads();
    }
}

// ============================================================
// launch
// ============================================================
extern "C" void kernel_launch(void* const* d_in, const int* in_sizes, int n_in,
                              void* d_out, int out_size)
{
    const float* x      = (const float*)d_in[0];
    const float* KV     = (const float*)d_in[1];
    const float* mask   = (const float*)d_in[2];
    const float* Wq     = (const float*)d_in[3];
    const float* bq     = (const float*)d_in[4];
    const float* Wkv    = (const float*)d_in[5];
    const float* bkv    = (const float*)d_in[6];
    const float* Wp     = (const float*)d_in[7];
    const float* bp     = (const float*)d_in[8];
    const float* cpb_w1 = (const float*)d_in[9];
    const float* cpb_b1 = (const float*)d_in[10];
    const float* cpb_w2 = (const float*)d_in[11];
    const float* cpb_b2 = (const float*)d_in[12];
    const float* tau    = (const float*)d_in[13];
    const float* lri    = (const float*)d_in[14];
    float* out = (float*)d_out;

    const int MROWS = BWIN * NTOK;       // 131072
    const int MT = MROWS / 128;          // 1024

    prep_w_kernel<<<1024, 256>>>(Wq, Wkv, Wp);
    bias_kernel<<<(NTOK*NTOK + 255)/256, 256>>>(cpb_w1, cpb_b1, cpb_w2, cpb_b2, tau, lri);
    mma_gemm_kernel<<<dim3(2, MT), 256>>>(x,  bq,  nullptr, 256, 0, 0);
    mma_gemm_kernel<<<dim3(4, MT), 256>>>(KV, bkv, nullptr, 512, 1, 65536);
    attn_mma_kernel<<<dim3(512, HEADS), 128>>>(mask);
    mma_gemm_kernel<<<dim3(2, MT), 256>>>(nullptr, bp, out, 256, 2, 196608);
}

// round 5
// speedup vs baseline: 3.2046x; 1.0022x over previous
#include <cuda_runtime.h>
#include <cuda_bf16.h>
#include <cstdint>

#define BWIN 2048
#define NTOK 64
#define DIM  256
#define HEADS 8
#define HD   32
#define NW   64

// ---- scratch (device globals; no allocations allowed) ----
__device__ float g_q [BWIN*HEADS*NTOK*HD];   // (b,h,n,d)
__device__ float g_k [BWIN*HEADS*NTOK*HD];
__device__ float g_v [BWIN*HEADS*NTOK*HD];
__device__ float g_ao[BWIN*NTOK*DIM];        // (b,n,c)
__device__ float g_bias  [HEADS*NTOK*NTOK];
__device__ float g_invtau[HEADS*NTOK*NTOK];
// pre-split weights: [Wq | Wkv | Wp] = 65536 + 131072 + 65536
__device__ __nv_bfloat16 g_wbh[262144];
__device__ __nv_bfloat16 g_wbl[262144];

// ============================================================
// helpers
// ============================================================
__device__ __forceinline__ void mma16816(float* c, const uint32_t* a, const uint32_t* b) {
    asm volatile("mma.sync.aligned.m16n8k16.row.col.f32.bf16.bf16.f32 "
        "{%0,%1,%2,%3}, {%4,%5,%6,%7}, {%8,%9}, {%0,%1,%2,%3};\n"
        : "+f"(c[0]), "+f"(c[1]), "+f"(c[2]), "+f"(c[3])
        : "r"(a[0]), "r"(a[1]), "r"(a[2]), "r"(a[3]), "r"(b[0]), "r"(b[1]));
}
__device__ __forceinline__ void ldsm_x4(uint32_t* r, uint32_t addr) {
    asm volatile("ldmatrix.sync.aligned.m8n8.x4.shared.b16 {%0,%1,%2,%3}, [%4];"
        : "=r"(r[0]), "=r"(r[1]), "=r"(r[2]), "=r"(r[3]) : "r"(addr));
}
__device__ __forceinline__ void ldsm_x2(uint32_t* r, uint32_t addr) {
    asm volatile("ldmatrix.sync.aligned.m8n8.x2.shared.b16 {%0,%1}, [%2];"
        : "=r"(r[0]), "=r"(r[1]) : "r"(addr));
}
__device__ __forceinline__ void ldsm_x2t(uint32_t* r, uint32_t addr) {
    asm volatile("ldmatrix.sync.aligned.m8n8.x2.trans.shared.b16 {%0,%1}, [%2];"
        : "=r"(r[0]), "=r"(r[1]) : "r"(addr));
}
__device__ __forceinline__ uint32_t pack_hi(float a, float b, float& ra, float& rb) {
    __nv_bfloat16 ha = __float2bfloat16_rn(a);
    __nv_bfloat16 hb = __float2bfloat16_rn(b);
    ra = a - __bfloat162float(ha);
    rb = b - __bfloat162float(hb);
    return ((uint32_t)__bfloat16_as_ushort(hb) << 16) | (uint32_t)__bfloat16_as_ushort(ha);
}
__device__ __forceinline__ uint32_t pack2(float a, float b) {
    return ((uint32_t)__bfloat16_as_ushort(__float2bfloat16_rn(b)) << 16)
         | (uint32_t)__bfloat16_as_ushort(__float2bfloat16_rn(a));
}

// ============================================================
// Kernel 0: pre-split weights to bf16 h/l
// ============================================================
__global__ void prep_w_kernel(const float* __restrict__ Wq,
                              const float* __restrict__ Wkv,
                              const float* __restrict__ Wp)
{
    int i = blockIdx.x * 256 + threadIdx.x;
    if (i >= 262144) return;
    float f;
    if (i < 65536) f = Wq[i];
    else if (i < 196608) f = Wkv[i - 65536];
    else f = Wp[i - 196608];
    __nv_bfloat16 hh = __float2bfloat16_rn(f);
    g_wbh[i] = hh;
    g_wbl[i] = __float2bfloat16_rn(f - __bfloat162float(hh));
}

// ============================================================
// Kernel 1: CPB bias MLP + inv-tau tables
// ============================================================
__global__ void bias_kernel(const float* __restrict__ w1, const float* __restrict__ b1,
                            const float* __restrict__ w2, const float* __restrict__ b2,
                            const float* __restrict__ tau, const float* __restrict__ lri)
{
    int idx = blockIdx.x * blockDim.x + threadIdx.x;
    if (idx >= NTOK*NTOK) return;
    float r0 = lri[idx*2 + 0];
    float r1 = lri[idx*2 + 1];
    float acc[HEADS];
    #pragma unroll
    for (int h = 0; h < HEADS; h++) acc[h] = 0.f;
    for (int k = 0; k < 256; k++) {
        float hk = fmaxf(r0 * w1[k] + r1 * w1[256 + k] + b1[k], 0.f);
        #pragma unroll
        for (int h = 0; h < HEADS; h++) acc[h] += hk * w2[k*HEADS + h];
    }
    #pragma unroll
    for (int h = 0; h < HEADS; h++) {
        g_bias[h*NTOK*NTOK + idx] = acc[h] + b2[h];
        g_invtau[h*NTOK*NTOK + idx] = 1.0f / fmaxf(tau[h*NTOK*NTOK + idx], 0.01f);
    }
}

// ============================================================
// Kernel 2: projection GEMM (bf16 split, preconverted weights)
//   reordered mma streams: dependency distance 16
// ============================================================
__device__ __forceinline__ void store_pair(int mode, int r, int c, float v0, float v1,
                                           const float* __restrict__ bias,
                                           float* __restrict__ D)
{
    v0 += bias[c]; v1 += bias[c + 1];
    int bI = r >> 6, nI = r & 63;
    if (mode == 0) {
        const float scale = 0.17677669529663687f;
        int h = c >> 5, d = c & 31;
        *(float2*)&g_q[(((size_t)bI*HEADS + h)*NTOK + nI)*HD + d] =
            make_float2(v0*scale, v1*scale);
    } else if (mode == 1) {
        if (c < 256) {
            int h = c >> 5, d = c & 31;
            *(float2*)&g_k[(((size_t)bI*HEADS + h)*NTOK + nI)*HD + d] = make_float2(v0, v1);
        } else {
            int c2 = c - 256;
            int h = c2 >> 5, d = c2 & 31;
            *(float2*)&g_v[(((size_t)bI*HEADS + h)*NTOK + nI)*HD + d] = make_float2(v0, v1);
        }
    } else {
        *(float2*)&D[(size_t)r*DIM + c] = make_float2(v0, v1);
    }
}

__global__ void __launch_bounds__(256) mma_gemm_kernel(
    const float* __restrict__ A,
    const float* __restrict__ bias, float* __restrict__ D,
    int ldb, int mode, int woff)
{
    __shared__ alignas(16) char As_h[4096];
    __shared__ alignas(16) char As_l[4096];
    __shared__ alignas(16) char Bs_h[4096];
    __shared__ alignas(16) char Bs_l[4096];

    const float* Ap = (mode == 2) ? g_ao : A;
    int tid = threadIdx.x;
    int lane = tid & 31, wid = tid >> 5;
    int warp_m = wid >> 1, warp_n = wid & 1;
    int row0 = blockIdx.y * 128;
    int col0 = blockIdx.x * 128;

    int m_a = tid >> 2;
    int c_a = tid & 3;
    int k_b2 = tid >> 4;          // 0..15
    int n_b2 = (tid & 15) * 8;    // 0..120

    float acc[2][8][4];
    #pragma unroll
    for (int mt = 0; mt < 2; mt++)
        #pragma unroll
        for (int nt = 0; nt < 8; nt++)
            #pragma unroll
            for (int i = 0; i < 4; i++) acc[mt][nt][i] = 0.f;

    uint32_t aaddr_h[2], aaddr_l[2];
    {
        int lrow_loc = ((lane >> 3) & 1) * 8 + (lane & 7);
        int lkh = lane >> 4;
        #pragma unroll
        for (int mt = 0; mt < 2; mt++) {
            int m = warp_m * 32 + mt * 16 + lrow_loc;
            uint32_t off = (uint32_t)m * 32u + (uint32_t)((lkh ^ ((m >> 2) & 1)) << 4);
            aaddr_h[mt] = (uint32_t)__cvta_generic_to_shared(As_h + off);
            aaddr_l[mt] = (uint32_t)__cvta_generic_to_shared(As_l + off);
        }
    }
    int bk_lane = lane & 15;
    uint32_t bbase_h = (uint32_t)__cvta_generic_to_shared(Bs_h) + (uint32_t)bk_lane * 256u;
    uint32_t bbase_l = (uint32_t)__cvta_generic_to_shared(Bs_l) + (uint32_t)bk_lane * 256u;
    int bkm = bk_lane & 7;

    const __nv_bfloat16* Bh = g_wbh + woff;
    const __nv_bfloat16* Bl = g_wbl + woff;

    float4 a0f, a1f;
    uint4 b_h, b_l;
    a0f = *(const float4*)(Ap + (size_t)(row0 + m_a)      * DIM + 4*c_a);
    a1f = *(const float4*)(Ap + (size_t)(row0 + m_a + 64) * DIM + 4*c_a);
    b_h = *(const uint4*)(Bh + (size_t)k_b2 * ldb + col0 + n_b2);
    b_l = *(const uint4*)(Bl + (size_t)k_b2 * ldb + col0 + n_b2);

    int kh_a = c_a >> 1;
    uint32_t offA0 = (uint32_t)m_a*32u        + (uint32_t)((kh_a ^ ((m_a >> 2) & 1)) << 4)        + (uint32_t)(c_a & 1) * 8u;
    uint32_t offA1 = (uint32_t)(m_a+64)*32u   + (uint32_t)((kh_a ^ (((m_a+64) >> 2) & 1)) << 4)   + (uint32_t)(c_a & 1) * 8u;
    uint32_t offB  = (uint32_t)k_b2*256u + (uint32_t)(((n_b2 >> 3) ^ (k_b2 & 7)) << 4);

    for (int kc = 0; kc < DIM/16; kc++) {
        {
            float r0, r1, r2, r3;
            uint32_t h0 = pack_hi(a0f.x, a0f.y, r0, r1);
            uint32_t h1 = pack_hi(a0f.z, a0f.w, r2, r3);
            *(uint2*)(As_h + offA0) = make_uint2(h0, h1);
            *(uint2*)(As_l + offA0) = make_uint2(pack2(r0, r1), pack2(r2, r3));
            h0 = pack_hi(a1f.x, a1f.y, r0, r1);
            h1 = pack_hi(a1f.z, a1f.w, r2, r3);
            *(uint2*)(As_h + offA1) = make_uint2(h0, h1);
            *(uint2*)(As_l + offA1) = make_uint2(pack2(r0, r1), pack2(r2, r3));
            *(uint4*)(Bs_h + offB) = b_h;
            *(uint4*)(Bs_l + offB) = b_l;
        }
        __syncthreads();

        if (kc + 1 < DIM/16) {
            int k0 = (kc + 1) * 16;
            a0f = *(const float4*)(Ap + (size_t)(row0 + m_a)      * DIM + k0 + 4*c_a);
            a1f = *(const float4*)(Ap + (size_t)(row0 + m_a + 64) * DIM + k0 + 4*c_a);
            b_h = *(const uint4*)(Bh + (size_t)(k0 + k_b2) * ldb + col0 + n_b2);
            b_l = *(const uint4*)(Bl + (size_t)(k0 + k_b2) * ldb + col0 + n_b2);
        }

        // preload ALL fragments, then issue mma streams with distance 16
        uint32_t ah[2][4], al[2][4];
        uint32_t bh2[8][2], bl2[8][2];
        ldsm_x4(ah[0], aaddr_h[0]);
        ldsm_x4(ah[1], aaddr_h[1]);
        ldsm_x4(al[0], aaddr_l[0]);
        ldsm_x4(al[1], aaddr_l[1]);
        #pragma unroll
        for (int nt = 0; nt < 8; nt++) {
            uint32_t boff = (uint32_t)(((warp_n*8 + nt) ^ bkm) << 4);
            ldsm_x2t(bh2[nt], bbase_h + boff);
            ldsm_x2t(bl2[nt], bbase_l + boff);
        }
        #pragma unroll
        for (int nt = 0; nt < 8; nt++) mma16816(acc[0][nt], ah[0], bh2[nt]);
        #pragma unroll
        for (int nt = 0; nt < 8; nt++) mma16816(acc[1][nt], ah[1], bh2[nt]);
        #pragma unroll
        for (int nt = 0; nt < 8; nt++) mma16816(acc[0][nt], ah[0], bl2[nt]);
        #pragma unroll
        for (int nt = 0; nt < 8; nt++) mma16816(acc[1][nt], ah[1], bl2[nt]);
        #pragma unroll
        for (int nt = 0; nt < 8; nt++) mma16816(acc[0][nt], al[0], bh2[nt]);
        #pragma unroll
        for (int nt = 0; nt < 8; nt++) mma16816(acc[1][nt], al[1], bh2[nt]);
        __syncthreads();
    }

    #pragma unroll
    for (int mt = 0; mt < 2; mt++) {
        int r_base = row0 + warp_m*32 + mt*16 + (lane >> 2);
        #pragma unroll
        for (int nt = 0; nt < 8; nt++) {
            int c_base = col0 + warp_n*64 + nt*8 + 2*(lane & 3);
            store_pair(mode, r_base,     c_base, acc[mt][nt][0], acc[mt][nt][1], bias, D);
            store_pair(mode, r_base + 8, c_base, acc[mt][nt][2], acc[mt][nt][3], bias, D);
        }
    }
}

// ============================================================
// Kernel 3: tensor-core attention, 4 warps/CTA, 4 windows/CTA
// ============================================================
__device__ __forceinline__ void store_cvt16(char* sm, int r, int d0, const float* f) {
    #pragma unroll
    for (int u = 0; u < 2; u++) {
        int o = u * 8;
        float rr[8];
        uint4 H, L;
        H.x = pack_hi(f[o+0], f[o+1], rr[0], rr[1]);
        H.y = pack_hi(f[o+2], f[o+3], rr[2], rr[3]);
        H.z = pack_hi(f[o+4], f[o+5], rr[4], rr[5]);
        H.w = pack_hi(f[o+6], f[o+7], rr[6], rr[7]);
        L.x = pack2(rr[0], rr[1]);
        L.y = pack2(rr[2], rr[3]);
        L.z = pack2(rr[4], rr[5]);
        L.w = pack2(rr[6], rr[7]);
        int ko = (d0 >> 3) + u;
        *(uint4*)(sm + r*128 + ((ko ^ (r & 7)) << 4))       = H;
        *(uint4*)(sm + r*128 + (((4 + ko) ^ (r & 7)) << 4)) = L;
    }
}

__global__ void __launch_bounds__(128) attn_mma_kernel(const float* __restrict__ mask)
{
    __shared__ alignas(16) char qsm[8192];
    __shared__ alignas(16) char ksm[8192];
    __shared__ alignas(16) char vsm[8192];
    __shared__ float qn_s[NTOK], kn_s[NTOK];

    int gx = blockIdx.x;                 // 0..511
    int h  = blockIdx.y;
    int w  = gx & 63, jg = gx >> 6;
    int tid = threadIdx.x;
    int lane = tid & 31, wid = tid >> 5;
    int mbase = wid * 16;

    uint32_t qsb = (uint32_t)__cvta_generic_to_shared(qsm);
    uint32_t ksb = (uint32_t)__cvta_generic_to_shared(ksm);
    uint32_t vsb = (uint32_t)__cvta_generic_to_shared(vsm);

    const float* itp = g_invtau + h*4096;
    const float* bpp = g_bias   + h*4096;
    const float* mpp = mask + (size_t)w*4096;

    int r_ld = tid >> 1;
    int d0   = (tid & 1) * 16;

    for (int t = 0; t < 4; t++) {
        int b = w + 64 * (jg * 4 + t);
        size_t base = ((size_t)(b*HEADS + h)) * (NTOK*HD);

        // ---- load + convert + norms ----
        {
            float f[16];
            const float* src = g_q + base + r_ld*HD + d0;
            *(float4*)(f)    = *(const float4*)(src);
            *(float4*)(f+4)  = *(const float4*)(src+4);
            *(float4*)(f+8)  = *(const float4*)(src+8);
            *(float4*)(f+12) = *(const float4*)(src+12);
            float ss = 0.f;
            #pragma unroll
            for (int i = 0; i < 16; i++) ss += f[i]*f[i];
            ss += __shfl_xor_sync(0xffffffffu, ss, 1);
            if ((tid & 1) == 0) qn_s[r_ld] = sqrtf(ss);
            store_cvt16(qsm, r_ld, d0, f);

            src = g_k + base + r_ld*HD + d0;
            *(float4*)(f)    = *(const float4*)(src);
            *(float4*)(f+4)  = *(const float4*)(src+4);
            *(float4*)(f+8)  = *(const float4*)(src+8);
            *(float4*)(f+12) = *(const float4*)(src+12);
            ss = 0.f;
            #pragma unroll
            for (int i = 0; i < 16; i++) ss += f[i]*f[i];
            ss += __shfl_xor_sync(0xffffffffu, ss, 1);
            if ((tid & 1) == 0) kn_s[r_ld] = sqrtf(ss);
            store_cvt16(ksm, r_ld, d0, f);

            src = g_v + base + r_ld*HD + d0;
            *(float4*)(f)    = *(const float4*)(src);
            *(float4*)(f+4)  = *(const float4*)(src+4);
            *(float4*)(f+8)  = *(const float4*)(src+8);
            *(float4*)(f+12) = *(const float4*)(src+12);
            store_cvt16(vsm, r_ld, d0, f);
        }
        __syncthreads();

        // ---- S = q k^T (preload fragments, long mma streams) ----
        float sf[8][4];
        #pragma unroll
        for (int nt = 0; nt < 8; nt++)
            #pragma unroll
            for (int i = 0; i < 4; i++) sf[nt][i] = 0.f;

        #pragma unroll
        for (int kt = 0; kt < 2; kt++) {
            int lrow = mbase + ((lane >> 3) & 1) * 8 + (lane & 7);
            int ko   = kt*2 + (lane >> 4);
            uint32_t ah[4], al[4];
            ldsm_x4(ah, qsb + lrow*128 + ((ko ^ (lrow & 7)) << 4));
            ldsm_x4(al, qsb + lrow*128 + (((4 + ko) ^ (lrow & 7)) << 4));
            int krow_l = (lane & 7);
            int kko    = kt*2 + ((lane >> 3) & 1);
            uint32_t kbh[8][2], kbl[8][2];
            #pragma unroll
            for (int nt = 0; nt < 8; nt++) {
                int krow = nt*8 + krow_l;
                ldsm_x2(kbh[nt], ksb + krow*128 + ((kko ^ (krow & 7)) << 4));
                ldsm_x2(kbl[nt], ksb + krow*128 + (((4 + kko) ^ (krow & 7)) << 4));
            }
            #pragma unroll
            for (int nt = 0; nt < 8; nt++) mma16816(sf[nt], ah, kbh[nt]);
            #pragma unroll
            for (int nt = 0; nt < 8; nt++) mma16816(sf[nt], ah, kbl[nt]);
            #pragma unroll
            for (int nt = 0; nt < 8; nt++) mma16816(sf[nt], al, kbh[nt]);
        }

        // ---- epilogue: cosine norm + tau + bias + mask ----
        int rA = mbase + (lane >> 2);
        int rB = rA + 8;
        float qnA = qn_s[rA], qnB = qn_s[rB];
        #pragma unroll
        for (int nt = 0; nt < 8; nt++) {
            int c0 = nt*8 + 2*(lane & 3);
            float2 kn2 = *(float2*)&kn_s[c0];
            int iA = rA*64 + c0, iB = rB*64 + c0;
            float2 tA = *(const float2*)(itp + iA);
            float2 tB = *(const float2*)(itp + iB);
            float2 bA = *(const float2*)(bpp + iA);
            float2 bB = *(const float2*)(bpp + iB);
            float2 mA = *(const float2*)(mpp + iA);
            float2 mB = *(const float2*)(mpp + iB);
            sf[nt][0] = __fdividef(sf[nt][0], fmaxf(qnA*kn2.x, 1e-6f)) * tA.x + bA.x + mA.x;
            sf[nt][1] = __fdividef(sf[nt][1], fmaxf(qnA*kn2.y, 1e-6f)) * tA.y + bA.y + mA.y;
            sf[nt][2] = __fdividef(sf[nt][2], fmaxf(qnB*kn2.x, 1e-6f)) * tB.x + bB.x + mB.x;
            sf[nt][3] = __fdividef(sf[nt][3], fmaxf(qnB*kn2.y, 1e-6f)) * tB.y + bB.y + mB.y;
        }

        // ---- fragment softmax (rows rA, rB) ----
        {
            float mA = -1e30f, mB = -1e30f;
            #pragma unroll
            for (int nt = 0; nt < 8; nt++) {
                mA = fmaxf(mA, fmaxf(sf[nt][0], sf[nt][1]));
                mB = fmaxf(mB, fmaxf(sf[nt][2], sf[nt][3]));
            }
            mA = fmaxf(mA, __shfl_xor_sync(0xffffffffu, mA, 1));
            mA = fmaxf(mA, __shfl_xor_sync(0xffffffffu, mA, 2));
            mB = fmaxf(mB, __shfl_xor_sync(0xffffffffu, mB, 1));
            mB = fmaxf(mB, __shfl_xor_sync(0xffffffffu, mB, 2));
            float sA = 0.f, sB = 0.f;
            #pragma unroll
            for (int nt = 0; nt < 8; nt++) {
                sf[nt][0] = __expf(sf[nt][0] - mA); sA += sf[nt][0];
                sf[nt][1] = __expf(sf[nt][1] - mA); sA += sf[nt][1];
                sf[nt][2] = __expf(sf[nt][2] - mB); sB += sf[nt][2];
                sf[nt][3] = __expf(sf[nt][3] - mB); sB += sf[nt][3];
            }
            sA += __shfl_xor_sync(0xffffffffu, sA, 1);
            sA += __shfl_xor_sync(0xffffffffu, sA, 2);
            sB += __shfl_xor_sync(0xffffffffu, sB, 1);
            sB += __shfl_xor_sync(0xffffffffu, sB, 2);
            float iA2 = __fdividef(1.f, sA);
            float iB2 = __fdividef(1.f, sB);
            #pragma unroll
            for (int nt = 0; nt < 8; nt++) {
                sf[nt][0] *= iA2; sf[nt][1] *= iA2;
                sf[nt][2] *= iB2; sf[nt][3] *= iB2;
            }
        }

        // ---- O = P V (preload v fragments per kt2) ----
        float of[4][4];
        #pragma unroll
        for (int nt = 0; nt < 4; nt++)
            #pragma unroll
            for (int i = 0; i < 4; i++) of[nt][i] = 0.f;

        #pragma unroll
        for (int kt2 = 0; kt2 < 4; kt2++) {
            int ntA = 2*kt2, ntB = 2*kt2 + 1;
            uint32_t pah[4], pal[4];
            float r0, r1;
            pah[0] = pack_hi(sf[ntA][0], sf[ntA][1], r0, r1); pal[0] = pack2(r0, r1);
            pah[1] = pack_hi(sf[ntA][2], sf[ntA][3], r0, r1); pal[1] = pack2(r0, r1);
            pah[2] = pack_hi(sf[ntB][0], sf[ntB][1], r0, r1); pal[2] = pack2(r0, r1);
            pah[3] = pack_hi(sf[ntB][2], sf[ntB][3], r0, r1); pal[3] = pack2(r0, r1);
            int vrow = kt2*16 + (lane & 15);
            int vsw = vrow & 7;
            uint32_t vbh[4][2], vbl[4][2];
            #pragma unroll
            for (int nt2 = 0; nt2 < 4; nt2++) {
                ldsm_x2t(vbh[nt2], vsb + vrow*128 + ((nt2 ^ vsw) << 4));
                ldsm_x2t(vbl[nt2], vsb + vrow*128 + (((4 + nt2) ^ vsw) << 4));
            }
            #pragma unroll
            for (int nt2 = 0; nt2 < 4; nt2++) mma16816(of[nt2], pah, vbh[nt2]);
            #pragma unroll
            for (int nt2 = 0; nt2 < 4; nt2++) mma16816(of[nt2], pah, vbl[nt2]);
            #pragma unroll
            for (int nt2 = 0; nt2 < 4; nt2++) mma16816(of[nt2], pal, vbh[nt2]);
        }

        // ---- store O ----
        {
            float* ob = g_ao + ((size_t)b*NTOK)*DIM + h*HD;
            #pragma unroll
            for (int nt2 = 0; nt2 < 4; nt2++) {
                int c = nt2*8 + 2*(lane & 3);
                *(float2*)(ob + (size_t)rA*DIM + c) = make_float2(of[nt2][0], of[nt2][1]);
                *(float2*)(ob + (size_t)rB*DIM + c) = make_float2(of[nt2][2], of[nt2][3]);
            }
        }
        __syncthreads();
    }
}

// ============================================================
// launch
// ============================================================
extern "C" void kernel_launch(void* const* d_in, const int* in_sizes, int n_in,
                              void* d_out, int out_size)
{
    const float* x      = (const float*)d_in[0];
    const float* KV     = (const float*)d_in[1];
    const float* mask   = (const float*)d_in[2];
    const float* Wq     = (const float*)d_in[3];
    const float* bq     = (const float*)d_in[4];
    const float* Wkv    = (const float*)d_in[5];
    const float* bkv    = (const float*)d_in[6];
    const float* Wp     = (const float*)d_in[7];
    const float* bp     = (const float*)d_in[8];
    const float* cpb_w1 = (const float*)d_in[9];
    const float* cpb_b1 = (const float*)d_in[10];
    const float* cpb_w2 = (const float*)d_in[11];
    const float* cpb_b2 = (const float*)d_in[12];
    const float* tau    = (const float*)d_in[13];
    const float* lri    = (const float*)d_in[14];
    float* out = (float*)d_out;

    const int MROWS = BWIN * NTOK;       // 131072
    const int MT = MROWS / 128;          // 1024

    prep_w_kernel<<<1024, 256>>>(Wq, Wkv, Wp);
    bias_kernel<<<(NTOK*NTOK + 255)/256, 256>>>(cpb_w1, cpb_b1, cpb_w2, cpb_b2, tau, lri);
    mma_gemm_kernel<<<dim3(2, MT), 256>>>(x,  bq,  nullptr, 256, 0, 0);
    mma_gemm_kernel<<<dim3(4, MT), 256>>>(KV, bkv, nullptr, 512, 1, 65536);
    attn_mma_kernel<<<dim3(512, HEADS), 128>>>(mask);
    mma_gemm_kernel<<<dim3(2, MT), 256>>>(nullptr, bp, out, 256, 2, 196608);
}

// round 6
// speedup vs baseline: 3.6214x; 1.1301x over previous
#include <cuda_runtime.h>
#include <cuda_bf16.h>
#include <cstdint>

#define BWIN 2048
#define NTOK 64
#define DIM  256
#define HEADS 8
#define HD   32
#define NW   64

// ---- scratch (device globals; no allocations allowed) ----
__device__ float g_q [BWIN*HEADS*NTOK*HD];   // (b,h,n,d)
__device__ float g_k [BWIN*HEADS*NTOK*HD];
__device__ float g_v [BWIN*HEADS*NTOK*HD];
__device__ float g_ao[BWIN*NTOK*DIM];        // (b,n,c)
__device__ float g_bias  [HEADS*NTOK*NTOK];
__device__ float g_invtau[HEADS*NTOK*NTOK];
// pre-split weights: [Wq | Wkv | Wp] = 65536 + 131072 + 65536
__device__ __nv_bfloat16 g_wbh[262144];
__device__ __nv_bfloat16 g_wbl[262144];

// ============================================================
// helpers
// ============================================================
__device__ __forceinline__ void mma16816(float* c, const uint32_t* a, const uint32_t* b) {
    asm volatile("mma.sync.aligned.m16n8k16.row.col.f32.bf16.bf16.f32 "
        "{%0,%1,%2,%3}, {%4,%5,%6,%7}, {%8,%9}, {%0,%1,%2,%3};\n"
        : "+f"(c[0]), "+f"(c[1]), "+f"(c[2]), "+f"(c[3])
        : "r"(a[0]), "r"(a[1]), "r"(a[2]), "r"(a[3]), "r"(b[0]), "r"(b[1]));
}
__device__ __forceinline__ void ldsm_x4(uint32_t* r, uint32_t addr) {
    asm volatile("ldmatrix.sync.aligned.m8n8.x4.shared.b16 {%0,%1,%2,%3}, [%4];"
        : "=r"(r[0]), "=r"(r[1]), "=r"(r[2]), "=r"(r[3]) : "r"(addr));
}
__device__ __forceinline__ void ldsm_x2(uint32_t* r, uint32_t addr) {
    asm volatile("ldmatrix.sync.aligned.m8n8.x2.shared.b16 {%0,%1}, [%2];"
        : "=r"(r[0]), "=r"(r[1]) : "r"(addr));
}
__device__ __forceinline__ void ldsm_x2t(uint32_t* r, uint32_t addr) {
    asm volatile("ldmatrix.sync.aligned.m8n8.x2.trans.shared.b16 {%0,%1}, [%2];"
        : "=r"(r[0]), "=r"(r[1]) : "r"(addr));
}
__device__ __forceinline__ void cp16(uint32_t smem, const void* gmem) {
    asm volatile("cp.async.cg.shared.global [%0], [%1], 16;" :: "r"(smem), "l"(gmem));
}
__device__ __forceinline__ void cp_commit() {
    asm volatile("cp.async.commit_group;");
}
__device__ __forceinline__ void cp_wait0() {
    asm volatile("cp.async.wait_group 0;");
}
__device__ __forceinline__ uint32_t pack_hi(float a, float b, float& ra, float& rb) {
    __nv_bfloat16 ha = __float2bfloat16_rn(a);
    __nv_bfloat16 hb = __float2bfloat16_rn(b);
    ra = a - __bfloat162float(ha);
    rb = b - __bfloat162float(hb);
    return ((uint32_t)__bfloat16_as_ushort(hb) << 16) | (uint32_t)__bfloat16_as_ushort(ha);
}
__device__ __forceinline__ uint32_t pack2(float a, float b) {
    return ((uint32_t)__bfloat16_as_ushort(__float2bfloat16_rn(b)) << 16)
         | (uint32_t)__bfloat16_as_ushort(__float2bfloat16_rn(a));
}

// ============================================================
// Kernel 0: pre-split weights to bf16 h/l
// ============================================================
__global__ void prep_w_kernel(const float* __restrict__ Wq,
                              const float* __restrict__ Wkv,
                              const float* __restrict__ Wp)
{
    int i = blockIdx.x * 256 + threadIdx.x;
    if (i >= 262144) return;
    float f;
    if (i < 65536) f = Wq[i];
    else if (i < 196608) f = Wkv[i - 65536];
    else f = Wp[i - 196608];
    __nv_bfloat16 hh = __float2bfloat16_rn(f);
    g_wbh[i] = hh;
    g_wbl[i] = __float2bfloat16_rn(f - __bfloat162float(hh));
}

// ============================================================
// Kernel 1: CPB bias MLP + inv-tau tables
// ============================================================
__global__ void bias_kernel(const float* __restrict__ w1, const float* __restrict__ b1,
                            const float* __restrict__ w2, const float* __restrict__ b2,
                            const float* __restrict__ tau, const float* __restrict__ lri)
{
    int idx = blockIdx.x * blockDim.x + threadIdx.x;
    if (idx >= NTOK*NTOK) return;
    float r0 = lri[idx*2 + 0];
    float r1 = lri[idx*2 + 1];
    float acc[HEADS];
    #pragma unroll
    for (int h = 0; h < HEADS; h++) acc[h] = 0.f;
    for (int k = 0; k < 256; k++) {
        float hk = fmaxf(r0 * w1[k] + r1 * w1[256 + k] + b1[k], 0.f);
        #pragma unroll
        for (int h = 0; h < HEADS; h++) acc[h] += hk * w2[k*HEADS + h];
    }
    #pragma unroll
    for (int h = 0; h < HEADS; h++) {
        g_bias[h*NTOK*NTOK + idx] = acc[h] + b2[h];
        g_invtau[h*NTOK*NTOK + idx] = 1.0f / fmaxf(tau[h*NTOK*NTOK + idx], 0.01f);
    }
}

// ============================================================
// Kernel 2: projection GEMM — double-buffered pipeline:
//   B via cp.async (pre-split bf16), A fp32->regs->convert->STS,
//   one compute phase per chunk with staggered convert.
// ============================================================
__device__ __forceinline__ void store_pair(int mode, int r, int c, float v0, float v1,
                                           const float* __restrict__ bias,
                                           float* __restrict__ D)
{
    v0 += bias[c]; v1 += bias[c + 1];
    int bI = r >> 6, nI = r & 63;
    if (mode == 0) {
        const float scale = 0.17677669529663687f;
        int h = c >> 5, d = c & 31;
        *(float2*)&g_q[(((size_t)bI*HEADS + h)*NTOK + nI)*HD + d] =
            make_float2(v0*scale, v1*scale);
    } else if (mode == 1) {
        if (c < 256) {
            int h = c >> 5, d = c & 31;
            *(float2*)&g_k[(((size_t)bI*HEADS + h)*NTOK + nI)*HD + d] = make_float2(v0, v1);
        } else {
            int c2 = c - 256;
            int h = c2 >> 5, d = c2 & 31;
            *(float2*)&g_v[(((size_t)bI*HEADS + h)*NTOK + nI)*HD + d] = make_float2(v0, v1);
        }
    } else {
        *(float2*)&D[(size_t)r*DIM + c] = make_float2(v0, v1);
    }
}

__global__ void __launch_bounds__(256) mma_gemm_kernel(
    const float* __restrict__ A,
    const float* __restrict__ bias, float* __restrict__ D,
    int ldb, int mode, int woff)
{
    __shared__ alignas(16) char As_h[2][4096];
    __shared__ alignas(16) char As_l[2][4096];
    __shared__ alignas(16) char Bs_h[2][4096];
    __shared__ alignas(16) char Bs_l[2][4096];

    const float* Ap = (mode == 2) ? g_ao : A;
    int tid = threadIdx.x;
    int lane = tid & 31, wid = tid >> 5;
    int warp_m = wid >> 1, warp_n = wid & 1;
    int row0 = blockIdx.y * 128;
    int col0 = blockIdx.x * 128;

    int m_a = tid >> 2;
    int c_a = tid & 3;
    int k_b2 = tid >> 4;          // 0..15
    int n_b2 = (tid & 15) * 8;    // 0..120

    float acc[2][8][4];
    #pragma unroll
    for (int mt = 0; mt < 2; mt++)
        #pragma unroll
        for (int nt = 0; nt < 8; nt++)
            #pragma unroll
            for (int i = 0; i < 4; i++) acc[mt][nt][i] = 0.f;

    // ---- per-buffer ldmatrix lane addresses ----
    uint32_t aaddr_h[2][2], aaddr_l[2][2];   // [buf][mt]
    {
        int lrow_loc = ((lane >> 3) & 1) * 8 + (lane & 7);
        int lkh = lane >> 4;
        #pragma unroll
        for (int s = 0; s < 2; s++)
            #pragma unroll
            for (int mt = 0; mt < 2; mt++) {
                int m = warp_m * 32 + mt * 16 + lrow_loc;
                uint32_t off = (uint32_t)m * 32u + (uint32_t)((lkh ^ ((m >> 2) & 1)) << 4);
                aaddr_h[s][mt] = (uint32_t)__cvta_generic_to_shared(&As_h[s][0]) + off;
                aaddr_l[s][mt] = (uint32_t)__cvta_generic_to_shared(&As_l[s][0]) + off;
            }
    }
    int bk_lane = lane & 15;
    uint32_t bbase_h[2], bbase_l[2];
    #pragma unroll
    for (int s = 0; s < 2; s++) {
        bbase_h[s] = (uint32_t)__cvta_generic_to_shared(&Bs_h[s][0]) + (uint32_t)bk_lane * 256u;
        bbase_l[s] = (uint32_t)__cvta_generic_to_shared(&Bs_l[s][0]) + (uint32_t)bk_lane * 256u;
    }
    int bkm = bk_lane & 7;

    const __nv_bfloat16* Bh = g_wbh + woff;
    const __nv_bfloat16* Bl = g_wbl + woff;

    // smem store offsets (within a buffer)
    int kh_a = c_a >> 1;
    uint32_t offA0 = (uint32_t)m_a*32u        + (uint32_t)((kh_a ^ ((m_a >> 2) & 1)) << 4)        + (uint32_t)(c_a & 1) * 8u;
    uint32_t offA1 = (uint32_t)(m_a+64)*32u   + (uint32_t)((kh_a ^ (((m_a+64) >> 2) & 1)) << 4)   + (uint32_t)(c_a & 1) * 8u;
    uint32_t offB  = (uint32_t)k_b2*256u + (uint32_t)(((n_b2 >> 3) ^ (k_b2 & 7)) << 4);

    uint32_t stAh[2], stAl[2], stBh[2], stBl[2];
    #pragma unroll
    for (int s = 0; s < 2; s++) {
        stAh[s] = (uint32_t)__cvta_generic_to_shared(&As_h[s][0]);
        stAl[s] = (uint32_t)__cvta_generic_to_shared(&As_l[s][0]);
        stBh[s] = (uint32_t)__cvta_generic_to_shared(&Bs_h[s][0]) + offB;
        stBl[s] = (uint32_t)__cvta_generic_to_shared(&Bs_l[s][0]) + offB;
    }

    float4 a0f, a1f;

    // lambda-ish macro: convert regs -> STS into buffer s
#define STS_A(s)                                                             \
    {                                                                        \
        float r0, r1, r2, r3;                                                \
        uint32_t h0 = pack_hi(a0f.x, a0f.y, r0, r1);                         \
        uint32_t h1 = pack_hi(a0f.z, a0f.w, r2, r3);                         \
        *(uint2*)(As_h[s] + offA0) = make_uint2(h0, h1);                     \
        *(uint2*)(As_l[s] + offA0) = make_uint2(pack2(r0, r1), pack2(r2, r3)); \
        h0 = pack_hi(a1f.x, a1f.y, r0, r1);                                  \
        h1 = pack_hi(a1f.z, a1f.w, r2, r3);                                  \
        *(uint2*)(As_h[s] + offA1) = make_uint2(h0, h1);                     \
        *(uint2*)(As_l[s] + offA1) = make_uint2(pack2(r0, r1), pack2(r2, r3)); \
    }

    // ---- prologue: chunk 0 ----
    a0f = *(const float4*)(Ap + (size_t)(row0 + m_a)      * DIM + 4*c_a);
    a1f = *(const float4*)(Ap + (size_t)(row0 + m_a + 64) * DIM + 4*c_a);
    cp16(stBh[0], Bh + (size_t)k_b2 * ldb + col0 + n_b2);
    cp16(stBl[0], Bl + (size_t)k_b2 * ldb + col0 + n_b2);
    cp_commit();
    STS_A(0);
    // prefetch chunk 1 A
    a0f = *(const float4*)(Ap + (size_t)(row0 + m_a)      * DIM + 16 + 4*c_a);
    a1f = *(const float4*)(Ap + (size_t)(row0 + m_a + 64) * DIM + 16 + 4*c_a);
    cp_wait0();
    __syncthreads();

    for (int kc = 0; kc < DIM/16; kc++) {
        int cur = kc & 1, nxt = cur ^ 1;
        bool has_next = (kc + 1 < DIM/16);

        if (has_next) {
            int k0 = (kc + 1) * 16;
            cp16(stBh[nxt], Bh + (size_t)(k0 + k_b2) * ldb + col0 + n_b2);
            cp16(stBl[nxt], Bl + (size_t)(k0 + k_b2) * ldb + col0 + n_b2);
            cp_commit();
            STS_A(nxt);                          // regs hold chunk kc+1
            if (kc + 2 < DIM/16) {
                int k1 = (kc + 2) * 16;
                a0f = *(const float4*)(Ap + (size_t)(row0 + m_a)      * DIM + k1 + 4*c_a);
                a1f = *(const float4*)(Ap + (size_t)(row0 + m_a + 64) * DIM + k1 + 4*c_a);
            }
        }

        // ---- compute from buffer cur ----
        uint32_t ah[2][4], al[2][4];
        uint32_t bh2[8][2], bl2[8][2];
        ldsm_x4(ah[0], aaddr_h[cur][0]);
        ldsm_x4(ah[1], aaddr_h[cur][1]);
        ldsm_x4(al[0], aaddr_l[cur][0]);
        ldsm_x4(al[1], aaddr_l[cur][1]);
        #pragma unroll
        for (int nt = 0; nt < 8; nt++) {
            uint32_t boff = (uint32_t)(((warp_n*8 + nt) ^ bkm) << 4);
            ldsm_x2t(bh2[nt], bbase_h[cur] + boff);
            ldsm_x2t(bl2[nt], bbase_l[cur] + boff);
        }
        #pragma unroll
        for (int nt = 0; nt < 8; nt++) mma16816(acc[0][nt], ah[0], bh2[nt]);
        #pragma unroll
        for (int nt = 0; nt < 8; nt++) mma16816(acc[1][nt], ah[1], bh2[nt]);
        #pragma unroll
        for (int nt = 0; nt < 8; nt++) mma16816(acc[0][nt], ah[0], bl2[nt]);
        #pragma unroll
        for (int nt = 0; nt < 8; nt++) mma16816(acc[1][nt], ah[1], bl2[nt]);
        #pragma unroll
        for (int nt = 0; nt < 8; nt++) mma16816(acc[0][nt], al[0], bh2[nt]);
        #pragma unroll
        for (int nt = 0; nt < 8; nt++) mma16816(acc[1][nt], al[1], bh2[nt]);

        if (has_next) cp_wait0();
        __syncthreads();
    }
#undef STS_A

    #pragma unroll
    for (int mt = 0; mt < 2; mt++) {
        int r_base = row0 + warp_m*32 + mt*16 + (lane >> 2);
        #pragma unroll
        for (int nt = 0; nt < 8; nt++) {
            int c_base = col0 + warp_n*64 + nt*8 + 2*(lane & 3);
            store_pair(mode, r_base,     c_base, acc[mt][nt][0], acc[mt][nt][1], bias, D);
            store_pair(mode, r_base + 8, c_base, acc[mt][nt][2], acc[mt][nt][3], bias, D);
        }
    }
}

// ============================================================
// Kernel 3: tensor-core attention, 4 warps/CTA, 4 windows/CTA
// ============================================================
__device__ __forceinline__ void store_cvt16(char* sm, int r, int d0, const float* f) {
    #pragma unroll
    for (int u = 0; u < 2; u++) {
        int o = u * 8;
        float rr[8];
        uint4 H, L;
        H.x = pack_hi(f[o+0], f[o+1], rr[0], rr[1]);
        H.y = pack_hi(f[o+2], f[o+3], rr[2], rr[3]);
        H.z = pack_hi(f[o+4], f[o+5], rr[4], rr[5]);
        H.w = pack_hi(f[o+6], f[o+7], rr[6], rr[7]);
        L.x = pack2(rr[0], rr[1]);
        L.y = pack2(rr[2], rr[3]);
        L.z = pack2(rr[4], rr[5]);
        L.w = pack2(rr[6], rr[7]);
        int ko = (d0 >> 3) + u;
        *(uint4*)(sm + r*128 + ((ko ^ (r & 7)) << 4))       = H;
        *(uint4*)(sm + r*128 + (((4 + ko) ^ (r & 7)) << 4)) = L;
    }
}

__global__ void __launch_bounds__(128) attn_mma_kernel(const float* __restrict__ mask)
{
    __shared__ alignas(16) char qsm[8192];
    __shared__ alignas(16) char ksm[8192];
    __shared__ alignas(16) char vsm[8192];
    __shared__ float qn_s[NTOK], kn_s[NTOK];

    int gx = blockIdx.x;                 // 0..511
    int h  = blockIdx.y;
    int w  = gx & 63, jg = gx >> 6;
    int tid = threadIdx.x;
    int lane = tid & 31, wid = tid >> 5;
    int mbase = wid * 16;

    uint32_t qsb = (uint32_t)__cvta_generic_to_shared(qsm);
    uint32_t ksb = (uint32_t)__cvta_generic_to_shared(ksm);
    uint32_t vsb = (uint32_t)__cvta_generic_to_shared(vsm);

    const float* itp = g_invtau + h*4096;
    const float* bpp = g_bias   + h*4096;
    const float* mpp = mask + (size_t)w*4096;

    int r_ld = tid >> 1;
    int d0   = (tid & 1) * 16;

    for (int t = 0; t < 4; t++) {
        int b = w + 64 * (jg * 4 + t);
        size_t base = ((size_t)(b*HEADS + h)) * (NTOK*HD);

        // ---- load + convert + norms ----
        {
            float f[16];
            const float* src = g_q + base + r_ld*HD + d0;
            *(float4*)(f)    = *(const float4*)(src);
            *(float4*)(f+4)  = *(const float4*)(src+4);
            *(float4*)(f+8)  = *(const float4*)(src+8);
            *(float4*)(f+12) = *(const float4*)(src+12);
            float ss = 0.f;
            #pragma unroll
            for (int i = 0; i < 16; i++) ss += f[i]*f[i];
            ss += __shfl_xor_sync(0xffffffffu, ss, 1);
            if ((tid & 1) == 0) qn_s[r_ld] = sqrtf(ss);
            store_cvt16(qsm, r_ld, d0, f);

            src = g_k + base + r_ld*HD + d0;
            *(float4*)(f)    = *(const float4*)(src);
            *(float4*)(f+4)  = *(const float4*)(src+4);
            *(float4*)(f+8)  = *(const float4*)(src+8);
            *(float4*)(f+12) = *(const float4*)(src+12);
            ss = 0.f;
            #pragma unroll
            for (int i = 0; i < 16; i++) ss += f[i]*f[i];
            ss += __shfl_xor_sync(0xffffffffu, ss, 1);
            if ((tid & 1) == 0) kn_s[r_ld] = sqrtf(ss);
            store_cvt16(ksm, r_ld, d0, f);

            src = g_v + base + r_ld*HD + d0;
            *(float4*)(f)    = *(const float4*)(src);
            *(float4*)(f+4)  = *(const float4*)(src+4);
            *(float4*)(f+8)  = *(const float4*)(src+8);
            *(float4*)(f+12) = *(const float4*)(src+12);
            store_cvt16(vsm, r_ld, d0, f);
        }
        __syncthreads();

        // ---- S = q k^T ----
        float sf[8][4];
        #pragma unroll
        for (int nt = 0; nt < 8; nt++)
            #pragma unroll
            for (int i = 0; i < 4; i++) sf[nt][i] = 0.f;

        #pragma unroll
        for (int kt = 0; kt < 2; kt++) {
            int lrow = mbase + ((lane >> 3) & 1) * 8 + (lane & 7);
            int ko   = kt*2 + (lane >> 4);
            uint32_t ah[4], al[4];
            ldsm_x4(ah, qsb + lrow*128 + ((ko ^ (lrow & 7)) << 4));
            ldsm_x4(al, qsb + lrow*128 + (((4 + ko) ^ (lrow & 7)) << 4));
            int krow_l = (lane & 7);
            int kko    = kt*2 + ((lane >> 3) & 1);
            uint32_t kbh[8][2], kbl[8][2];
            #pragma unroll
            for (int nt = 0; nt < 8; nt++) {
                int krow = nt*8 + krow_l;
                ldsm_x2(kbh[nt], ksb + krow*128 + ((kko ^ (krow & 7)) << 4));
                ldsm_x2(kbl[nt], ksb + krow*128 + (((4 + kko) ^ (krow & 7)) << 4));
            }
            #pragma unroll
            for (int nt = 0; nt < 8; nt++) mma16816(sf[nt], ah, kbh[nt]);
            #pragma unroll
            for (int nt = 0; nt < 8; nt++) mma16816(sf[nt], ah, kbl[nt]);
            #pragma unroll
            for (int nt = 0; nt < 8; nt++) mma16816(sf[nt], al, kbh[nt]);
        }

        // ---- epilogue: cosine norm + tau + bias + mask ----
        int rA = mbase + (lane >> 2);
        int rB = rA + 8;
        float qnA = qn_s[rA], qnB = qn_s[rB];
        #pragma unroll
        for (int nt = 0; nt < 8; nt++) {
            int c0 = nt*8 + 2*(lane & 3);
            float2 kn2 = *(float2*)&kn_s[c0];
            int iA = rA*64 + c0, iB = rB*64 + c0;
            float2 tA = *(const float2*)(itp + iA);
            float2 tB = *(const float2*)(itp + iB);
            float2 bA = *(const float2*)(bpp + iA);
            float2 bB = *(const float2*)(bpp + iB);
            float2 mA = *(const float2*)(mpp + iA);
            float2 mB = *(const float2*)(mpp + iB);
            sf[nt][0] = __fdividef(sf[nt][0], fmaxf(qnA*kn2.x, 1e-6f)) * tA.x + bA.x + mA.x;
            sf[nt][1] = __fdividef(sf[nt][1], fmaxf(qnA*kn2.y, 1e-6f)) * tA.y + bA.y + mA.y;
            sf[nt][2] = __fdividef(sf[nt][2], fmaxf(qnB*kn2.x, 1e-6f)) * tB.x + bB.x + mB.x;
            sf[nt][3] = __fdividef(sf[nt][3], fmaxf(qnB*kn2.y, 1e-6f)) * tB.y + bB.y + mB.y;
        }

        // ---- fragment softmax (rows rA, rB) ----
        {
            float mA = -1e30f, mB = -1e30f;
            #pragma unroll
            for (int nt = 0; nt < 8; nt++) {
                mA = fmaxf(mA, fmaxf(sf[nt][0], sf[nt][1]));
                mB = fmaxf(mB, fmaxf(sf[nt][2], sf[nt][3]));
            }
            mA = fmaxf(mA, __shfl_xor_sync(0xffffffffu, mA, 1));
            mA = fmaxf(mA, __shfl_xor_sync(0xffffffffu, mA, 2));
            mB = fmaxf(mB, __shfl_xor_sync(0xffffffffu, mB, 1));
            mB = fmaxf(mB, __shfl_xor_sync(0xffffffffu, mB, 2));
            float sA = 0.f, sB = 0.f;
            #pragma unroll
            for (int nt = 0; nt < 8; nt++) {
                sf[nt][0] = __expf(sf[nt][0] - mA); sA += sf[nt][0];
                sf[nt][1] = __expf(sf[nt][1] - mA); sA += sf[nt][1];
                sf[nt][2] = __expf(sf[nt][2] - mB); sB += sf[nt][2];
                sf[nt][3] = __expf(sf[nt][3] - mB); sB += sf[nt][3];
            }
            sA += __shfl_xor_sync(0xffffffffu, sA, 1);
            sA += __shfl_xor_sync(0xffffffffu, sA, 2);
            sB += __shfl_xor_sync(0xffffffffu, sB, 1);
            sB += __shfl_xor_sync(0xffffffffu, sB, 2);
            float iA2 = __fdividef(1.f, sA);
            float iB2 = __fdividef(1.f, sB);
            #pragma unroll
            for (int nt = 0; nt < 8; nt++) {
                sf[nt][0] *= iA2; sf[nt][1] *= iA2;
                sf[nt][2] *= iB2; sf[nt][3] *= iB2;
            }
        }

        // ---- O = P V ----
        float of[4][4];
        #pragma unroll
        for (int nt = 0; nt < 4; nt++)
            #pragma unroll
            for (int i = 0; i < 4; i++) of[nt][i] = 0.f;

        #pragma unroll
        for (int kt2 = 0; kt2 < 4; kt2++) {
            int ntA = 2*kt2, ntB = 2*kt2 + 1;
            uint32_t pah[4], pal[4];
            float r0, r1;
            pah[0] = pack_hi(sf[ntA][0], sf[ntA][1], r0, r1); pal[0] = pack2(r0, r1);
            pah[1] = pack_hi(sf[ntA][2], sf[ntA][3], r0, r1); pal[1] = pack2(r0, r1);
            pah[2] = pack_hi(sf[ntB][0], sf[ntB][1], r0, r1); pal[2] = pack2(r0, r1);
            pah[3] = pack_hi(sf[ntB][2], sf[ntB][3], r0, r1); pal[3] = pack2(r0, r1);
            int vrow = kt2*16 + (lane & 15);
            int vsw = vrow & 7;
            uint32_t vbh[4][2], vbl[4][2];
            #pragma unroll
            for (int nt2 = 0; nt2 < 4; nt2++) {
                ldsm_x2t(vbh[nt2], vsb + vrow*128 + ((nt2 ^ vsw) << 4));
                ldsm_x2t(vbl[nt2], vsb + vrow*128 + (((4 + nt2) ^ vsw) << 4));
            }
            #pragma unroll
            for (int nt2 = 0; nt2 < 4; nt2++) mma16816(of[nt2], pah, vbh[nt2]);
            #pragma unroll
            for (int nt2 = 0; nt2 < 4; nt2++) mma16816(of[nt2], pah, vbl[nt2]);
            #pragma unroll
            for (int nt2 = 0; nt2 < 4; nt2++) mma16816(of[nt2], pal, vbh[nt2]);
        }

        // ---- store O ----
        {
            float* ob = g_ao + ((size_t)b*NTOK)*DIM + h*HD;
            #pragma unroll
            for (int nt2 = 0; nt2 < 4; nt2++) {
                int c = nt2*8 + 2*(lane & 3);
                *(float2*)(ob + (size_t)rA*DIM + c) = make_float2(of[nt2][0], of[nt2][1]);
                *(float2*)(ob + (size_t)rB*DIM + c) = make_float2(of[nt2][2], of[nt2][3]);
            }
        }
        __syncthreads();
    }
}

// ============================================================
// launch
// ============================================================
extern "C" void kernel_launch(void* const* d_in, const int* in_sizes, int n_in,
                              void* d_out, int out_size)
{
    const float* x      = (const float*)d_in[0];
    const float* KV     = (const float*)d_in[1];
    const float* mask   = (const float*)d_in[2];
    const float* Wq     = (const float*)d_in[3];
    const float* bq     = (const float*)d_in[4];
    const float* Wkv    = (const float*)d_in[5];
    const float* bkv    = (const float*)d_in[6];
    const float* Wp     = (const float*)d_in[7];
    const float* bp     = (const float*)d_in[8];
    const float* cpb_w1 = (const float*)d_in[9];
    const float* cpb_b1 = (const float*)d_in[10];
    const float* cpb_w2 = (const float*)d_in[11];
    const float* cpb_b2 = (const float*)d_in[12];
    const float* tau    = (const float*)d_in[13];
    const float* lri    = (const float*)d_in[14];
    float* out = (float*)d_out;

    const int MROWS = BWIN * NTOK;       // 131072
    const int MT = MROWS / 128;          // 1024

    prep_w_kernel<<<1024, 256>>>(Wq, Wkv, Wp);
    bias_kernel<<<(NTOK*NTOK + 255)/256, 256>>>(cpb_w1, cpb_b1, cpb_w2, cpb_b2, tau, lri);
    mma_gemm_kernel<<<dim3(2, MT), 256>>>(x,  bq,  nullptr, 256, 0, 0);
    mma_gemm_kernel<<<dim3(4, MT), 256>>>(KV, bkv, nullptr, 512, 1, 65536);
    attn_mma_kernel<<<dim3(512, HEADS), 128>>>(mask);
    mma_gemm_kernel<<<dim3(2, MT), 256>>>(nullptr, bp, out, 256, 2, 196608);
}

// round 8
// speedup vs baseline: 3.6454x; 1.0066x over previous
#include <cuda_runtime.h>
#include <cuda_bf16.h>
#include <cstdint>

#define BWIN 2048
#define NTOK 64
#define DIM  256
#define HEADS 8
#define HD   32
#define NW   64

// ---- scratch (device globals; no allocations allowed) ----
// q/k/v stored pre-split bf16 (h/l packed as bf16x2 words) + norms
__device__ uint32_t g_qh[BWIN*HEADS*NTOK*16];
__device__ uint32_t g_ql[BWIN*HEADS*NTOK*16];
__device__ uint32_t g_kh[BWIN*HEADS*NTOK*16];
__device__ uint32_t g_kl[BWIN*HEADS*NTOK*16];
__device__ uint32_t g_vh[BWIN*HEADS*NTOK*16];
__device__ uint32_t g_vl[BWIN*HEADS*NTOK*16];
__device__ float    g_qn[BWIN*HEADS*NTOK];
__device__ float    g_kn[BWIN*HEADS*NTOK];
__device__ float g_ao[BWIN*NTOK*DIM];        // (b,n,c)
__device__ float g_bias  [HEADS*NTOK*NTOK];
__device__ float g_invtau[HEADS*NTOK*NTOK];
// pre-split weights [K,N]: [Wq | Wkv | Wp] = 65536 + 131072 + 65536
__device__ __nv_bfloat16 g_wbh[262144];
__device__ __nv_bfloat16 g_wbl[262144];

// ============================================================
// helpers
// ============================================================
__device__ __forceinline__ void mma16816(float* c, const uint32_t* a, const uint32_t* b) {
    asm volatile("mma.sync.aligned.m16n8k16.row.col.f32.bf16.bf16.f32 "
        "{%0,%1,%2,%3}, {%4,%5,%6,%7}, {%8,%9}, {%0,%1,%2,%3};\n"
        : "+f"(c[0]), "+f"(c[1]), "+f"(c[2]), "+f"(c[3])
        : "r"(a[0]), "r"(a[1]), "r"(a[2]), "r"(a[3]), "r"(b[0]), "r"(b[1]));
}
__device__ __forceinline__ void ldsm_x4(uint32_t* r, uint32_t addr) {
    asm volatile("ldmatrix.sync.aligned.m8n8.x4.shared.b16 {%0,%1,%2,%3}, [%4];"
        : "=r"(r[0]), "=r"(r[1]), "=r"(r[2]), "=r"(r[3]) : "r"(addr));
}
__device__ __forceinline__ void ldsm_x2(uint32_t* r, uint32_t addr) {
    asm volatile("ldmatrix.sync.aligned.m8n8.x2.shared.b16 {%0,%1}, [%2];"
        : "=r"(r[0]), "=r"(r[1]) : "r"(addr));
}
__device__ __forceinline__ void ldsm_x2t(uint32_t* r, uint32_t addr) {
    asm volatile("ldmatrix.sync.aligned.m8n8.x2.trans.shared.b16 {%0,%1}, [%2];"
        : "=r"(r[0]), "=r"(r[1]) : "r"(addr));
}
__device__ __forceinline__ void cp16(uint32_t smem, const void* gmem) {
    asm volatile("cp.async.cg.shared.global [%0], [%1], 16;" :: "r"(smem), "l"(gmem));
}
__device__ __forceinline__ void cp_commit() { asm volatile("cp.async.commit_group;"); }
__device__ __forceinline__ void cp_wait0()  { asm volatile("cp.async.wait_group 0;"); }
__device__ __forceinline__ uint32_t pack_hi(float a, float b, float& ra, float& rb) {
    __nv_bfloat16 ha = __float2bfloat16_rn(a);
    __nv_bfloat16 hb = __float2bfloat16_rn(b);
    ra = a - __bfloat162float(ha);
    rb = b - __bfloat162float(hb);
    return ((uint32_t)__bfloat16_as_ushort(hb) << 16) | (uint32_t)__bfloat16_as_ushort(ha);
}
__device__ __forceinline__ uint32_t pack2(float a, float b) {
    return ((uint32_t)__bfloat16_as_ushort(__float2bfloat16_rn(b)) << 16)
         | (uint32_t)__bfloat16_as_ushort(__float2bfloat16_rn(a));
}

// ============================================================
// Kernel 0: pre-split weights to bf16 h/l ([K,N] layout)
// ============================================================
__global__ void prep_w_kernel(const float* __restrict__ Wq,
                              const float* __restrict__ Wkv,
                              const float* __restrict__ Wp)
{
    int i = blockIdx.x * 256 + threadIdx.x;
    if (i >= 262144) return;
    float f;
    if (i < 65536) f = Wq[i];
    else if (i < 196608) f = Wkv[i - 65536];
    else f = Wp[i - 196608];
    __nv_bfloat16 hh = __float2bfloat16_rn(f);
    g_wbh[i] = hh;
    g_wbl[i] = __float2bfloat16_rn(f - __bfloat162float(hh));
}

// ============================================================
// Kernel 1: CPB bias MLP + inv-tau tables
// ============================================================
__global__ void bias_kernel(const float* __restrict__ w1, const float* __restrict__ b1,
                            const float* __restrict__ w2, const float* __restrict__ b2,
                            const float* __restrict__ tau, const float* __restrict__ lri)
{
    int idx = blockIdx.x * blockDim.x + threadIdx.x;
    if (idx >= NTOK*NTOK) return;
    float r0 = lri[idx*2 + 0];
    float r1 = lri[idx*2 + 1];
    float acc[HEADS];
    #pragma unroll
    for (int h = 0; h < HEADS; h++) acc[h] = 0.f;
    for (int k = 0; k < 256; k++) {
        float hk = fmaxf(r0 * w1[k] + r1 * w1[256 + k] + b1[k], 0.f);
        #pragma unroll
        for (int h = 0; h < HEADS; h++) acc[h] += hk * w2[k*HEADS + h];
    }
    #pragma unroll
    for (int h = 0; h < HEADS; h++) {
        g_bias[h*NTOK*NTOK + idx] = acc[h] + b2[h];
        g_invtau[h*NTOK*NTOK + idx] = 1.0f / fmaxf(tau[h*NTOK*NTOK + idx], 0.01f);
    }
}

// ============================================================
// Kernel 2: projection GEMM
//   A: direct fragment LDG + in-reg convert (no smem for A)
//   B: pre-split bf16 via cp.async double buffer + ldmatrix
//   epilogue modes 0/1: pack bf16 h/l + fused row norms
// ============================================================
__global__ void __launch_bounds__(256, 2) mma_gemm_kernel(
    const float* __restrict__ A,
    const float* __restrict__ bias, float* __restrict__ D,
    int ldb, int mode, int woff)
{
    __shared__ alignas(16) char Bs_h[2][4096];
    __shared__ alignas(16) char Bs_l[2][4096];

    const float* Ap = (mode == 2) ? g_ao : A;
    int tid = threadIdx.x;
    int lane = tid & 31, wid = tid >> 5;
    int warp_m = wid >> 1, warp_n = wid & 1;
    int row0 = blockIdx.y * 128;
    int col0 = blockIdx.x * 128;

    // B fill roles
    int k_b2 = tid >> 4;          // 0..15
    int n_b2 = (tid & 15) * 8;    // 0..120
    uint32_t offB = (uint32_t)k_b2*256u + (uint32_t)(((n_b2 >> 3) ^ (k_b2 & 7)) << 4);
    uint32_t stBh[2], stBl[2];
    #pragma unroll
    for (int s = 0; s < 2; s++) {
        stBh[s] = (uint32_t)__cvta_generic_to_shared(&Bs_h[s][0]) + offB;
        stBl[s] = (uint32_t)__cvta_generic_to_shared(&Bs_l[s][0]) + offB;
    }
    int bk_lane = lane & 15;
    uint32_t bbase_h[2], bbase_l[2];
    #pragma unroll
    for (int s = 0; s < 2; s++) {
        bbase_h[s] = (uint32_t)__cvta_generic_to_shared(&Bs_h[s][0]) + (uint32_t)bk_lane * 256u;
        bbase_l[s] = (uint32_t)__cvta_generic_to_shared(&Bs_l[s][0]) + (uint32_t)bk_lane * 256u;
    }
    int bkm = bk_lane & 7;

    const __nv_bfloat16* Bh = g_wbh + woff;
    const __nv_bfloat16* Bl = g_wbl + woff;

    // A direct-load pointers (fragment-exact)
    const float* ap0 = Ap + (size_t)(row0 + warp_m*32 + (lane >> 2)) * DIM + (lane & 3) * 2;
    const float* ap1 = ap0 + 16 * DIM;   // mt=1

    float acc[2][8][4];
    #pragma unroll
    for (int mt = 0; mt < 2; mt++)
        #pragma unroll
        for (int nt = 0; nt < 8; nt++)
            #pragma unroll
            for (int i = 0; i < 4; i++) acc[mt][nt][i] = 0.f;

    float2 af[2][4];
#define LDA(kc)                                                         \
    {                                                                   \
        int kk = (kc) * 16;                                             \
        af[0][0] = *(const float2*)(ap0 + kk);                          \
        af[0][1] = *(const float2*)(ap0 + 8*DIM + kk);                  \
        af[0][2] = *(const float2*)(ap0 + kk + 8);                      \
        af[0][3] = *(const float2*)(ap0 + 8*DIM + kk + 8);              \
        af[1][0] = *(const float2*)(ap1 + kk);                          \
        af[1][1] = *(const float2*)(ap1 + 8*DIM + kk);                  \
        af[1][2] = *(const float2*)(ap1 + kk + 8);                      \
        af[1][3] = *(const float2*)(ap1 + 8*DIM + kk + 8);              \
    }

    // prologue: B chunk 0 + A chunk 0
    cp16(stBh[0], Bh + (size_t)k_b2 * ldb + col0 + n_b2);
    cp16(stBl[0], Bl + (size_t)k_b2 * ldb + col0 + n_b2);
    cp_commit();
    LDA(0);
    cp_wait0();
    __syncthreads();

    for (int kc = 0; kc < DIM/16; kc++) {
        int cur = kc & 1, nxt = cur ^ 1;
        bool has_next = (kc + 1 < DIM/16);

        if (has_next) {
            int k0 = (kc + 1) * 16;
            cp16(stBh[nxt], Bh + (size_t)(k0 + k_b2) * ldb + col0 + n_b2);
            cp16(stBl[nxt], Bl + (size_t)(k0 + k_b2) * ldb + col0 + n_b2);
            cp_commit();
        }

        // convert current A fragments
        uint32_t ah[2][4], al[2][4];
        #pragma unroll
        for (int mt = 0; mt < 2; mt++)
            #pragma unroll
            for (int j = 0; j < 4; j++) {
                float rx, ry;
                ah[mt][j] = pack_hi(af[mt][j].x, af[mt][j].y, rx, ry);
                al[mt][j] = pack2(rx, ry);
            }

        if (has_next) LDA(kc + 1);

        // compute from B buffer cur
        #pragma unroll
        for (int nt = 0; nt < 8; nt++) {
            uint32_t boff = (uint32_t)(((warp_n*8 + nt) ^ bkm) << 4);
            uint32_t bh2[2], bl2[2];
            ldsm_x2t(bh2, bbase_h[cur] + boff);
            ldsm_x2t(bl2, bbase_l[cur] + boff);
            mma16816(acc[0][nt], ah[0], bh2);
            mma16816(acc[1][nt], ah[1], bh2);
            mma16816(acc[0][nt], ah[0], bl2);
            mma16816(acc[1][nt], ah[1], bl2);
            mma16816(acc[0][nt], al[0], bh2);
            mma16816(acc[1][nt], al[1], bh2);
        }

        if (has_next) cp_wait0();
        __syncthreads();
    }
#undef LDA

    // ---- epilogue ----
    if (mode == 2) {
        #pragma unroll
        for (int mt = 0; mt < 2; mt++) {
            int r_base = row0 + warp_m*32 + mt*16 + (lane >> 2);
            #pragma unroll
            for (int nt = 0; nt < 8; nt++) {
                int c = col0 + warp_n*64 + nt*8 + 2*(lane & 3);
                float b0 = bias[c], b1 = bias[c+1];
                *(float2*)&D[(size_t)r_base*DIM + c] =
                    make_float2(acc[mt][nt][0]+b0, acc[mt][nt][1]+b1);
                *(float2*)&D[(size_t)(r_base+8)*DIM + c] =
                    make_float2(acc[mt][nt][2]+b0, acc[mt][nt][3]+b1);
            }
        }
    } else {
        const float scale = 0.17677669529663687f;
        #pragma unroll
        for (int mt = 0; mt < 2; mt++) {
            int rr = row0 + warp_m*32 + mt*16 + (lane >> 2);
            int bI = rr >> 6, nI = rr & 63;
            #pragma unroll
            for (int hg = 0; hg < 2; hg++) {
                int cg = col0 + warp_n*64 + hg*32;    // head base column
                float sqA = 0.f, sqB = 0.f;
                uint32_t hwA[4], lwA[4], hwB[4], lwB[4];
                #pragma unroll
                for (int j = 0; j < 4; j++) {
                    int nt = hg*4 + j;
                    int c = cg + j*8 + 2*(lane & 3);
                    float b0 = bias[c], b1 = bias[c+1];
                    float v0 = acc[mt][nt][0]+b0, v1 = acc[mt][nt][1]+b1;
                    float v2 = acc[mt][nt][2]+b0, v3 = acc[mt][nt][3]+b1;
                    if (mode == 0) { v0*=scale; v1*=scale; v2*=scale; v3*=scale; }
                    sqA += v0*v0 + v1*v1;
                    sqB += v2*v2 + v3*v3;
                    float rx, ry;
                    hwA[j] = pack_hi(v0, v1, rx, ry); lwA[j] = pack2(rx, ry);
                    hwB[j] = pack_hi(v2, v3, rx, ry); lwB[j] = pack2(rx, ry);
                }
                sqA += __shfl_xor_sync(0xffffffffu, sqA, 1);
                sqA += __shfl_xor_sync(0xffffffffu, sqA, 2);
                sqB += __shfl_xor_sync(0xffffffffu, sqB, 1);
                sqB += __shfl_xor_sync(0xffffffffu, sqB, 2);

                uint32_t *dh, *dl;
                float* dn = nullptr;
                int hh;
                if (mode == 0)      { hh = cg >> 5;         dh = g_qh; dl = g_ql; dn = g_qn; }
                else if (cg < 256)  { hh = cg >> 5;         dh = g_kh; dl = g_kl; dn = g_kn; }
                else                { hh = (cg - 256) >> 5; dh = g_vh; dl = g_vl; }

                size_t wb = (((size_t)bI*HEADS + hh)*NTOK + nI)*16 + (lane & 3);
                #pragma unroll
                for (int j = 0; j < 4; j++) {
                    dh[wb + j*4]        = hwA[j];
                    dl[wb + j*4]        = lwA[j];
                    dh[wb + 8*16 + j*4] = hwB[j];
                    dl[wb + 8*16 + j*4] = lwB[j];
                }
                if (dn && (lane & 3) == 0) {
                    size_t nb = ((size_t)bI*HEADS + hh)*NTOK + nI;
                    dn[nb]     = sqrtf(sqA);
                    dn[nb + 8] = sqrtf(sqB);
                }
            }
        }
    }
}

// ============================================================
// Kernel 3: tensor-core attention, pre-packed bf16 q/k/v
// ============================================================
__global__ void __launch_bounds__(128) attn_mma_kernel(const float* __restrict__ mask)
{
    __shared__ alignas(16) char qsm[8192];
    __shared__ alignas(16) char ksm[8192];
    __shared__ alignas(16) char vsm[8192];
    __shared__ float qn_s[NTOK], kn_s[NTOK];

    int gx = blockIdx.x;
    int h  = blockIdx.y;
    int w  = gx & 63, jg = gx >> 6;
    int tid = threadIdx.x;
    int lane = tid & 31, wid = tid >> 5;
    int mbase = wid * 16;

    uint32_t qsb = (uint32_t)__cvta_generic_to_shared(qsm);
    uint32_t ksb = (uint32_t)__cvta_generic_to_shared(ksm);
    uint32_t vsb = (uint32_t)__cvta_generic_to_shared(vsm);

    const float* itp = g_invtau + h*4096;
    const float* bpp = g_bias   + h*4096;
    const float* mpp = mask + (size_t)w*4096;

    int r_ld = tid >> 1;
    int half = tid & 1;
    int swr = r_ld & 7;
    int ko0 = half * 2;

    for (int t = 0; t < 4; t++) {
        int b = w + 64 * (jg * 4 + t);
        size_t wb = (((size_t)b*HEADS + h)*NTOK + r_ld)*16 + half*8;
        size_t nb = ((size_t)b*HEADS + h)*NTOK;

        // ---- fill: straight packed copies + norm loads ----
        {
            uint4 a0 = *(const uint4*)(g_qh + wb);
            uint4 a1 = *(const uint4*)(g_qh + wb + 4);
            uint4 b0 = *(const uint4*)(g_ql + wb);
            uint4 b1 = *(const uint4*)(g_ql + wb + 4);
            *(uint4*)(qsm + r_ld*128 + (((ko0+0) ^ swr) << 4))     = a0;
            *(uint4*)(qsm + r_ld*128 + (((ko0+1) ^ swr) << 4))     = a1;
            *(uint4*)(qsm + r_ld*128 + (((4+ko0+0) ^ swr) << 4))   = b0;
            *(uint4*)(qsm + r_ld*128 + (((4+ko0+1) ^ swr) << 4))   = b1;
            a0 = *(const uint4*)(g_kh + wb);
            a1 = *(const uint4*)(g_kh + wb + 4);
            b0 = *(const uint4*)(g_kl + wb);
            b1 = *(const uint4*)(g_kl + wb + 4);
            *(uint4*)(ksm + r_ld*128 + (((ko0+0) ^ swr) << 4))     = a0;
            *(uint4*)(ksm + r_ld*128 + (((ko0+1) ^ swr) << 4))     = a1;
            *(uint4*)(ksm + r_ld*128 + (((4+ko0+0) ^ swr) << 4))   = b0;
            *(uint4*)(ksm + r_ld*128 + (((4+ko0+1) ^ swr) << 4))   = b1;
            a0 = *(const uint4*)(g_vh + wb);
            a1 = *(const uint4*)(g_vh + wb + 4);
            b0 = *(const uint4*)(g_vl + wb);
            b1 = *(const uint4*)(g_vl + wb + 4);
            *(uint4*)(vsm + r_ld*128 + (((ko0+0) ^ swr) << 4))     = a0;
            *(uint4*)(vsm + r_ld*128 + (((ko0+1) ^ swr) << 4))     = a1;
            *(uint4*)(vsm + r_ld*128 + (((4+ko0+0) ^ swr) << 4))   = b0;
            *(uint4*)(vsm + r_ld*128 + (((4+ko0+1) ^ swr) << 4))   = b1;
            if (tid < 64) qn_s[tid] = g_qn[nb + tid];
            else          kn_s[tid - 64] = g_kn[nb + tid - 64];
        }
        __syncthreads();

        // ---- S = q k^T ----
        float sf[8][4];
        #pragma unroll
        for (int nt = 0; nt < 8; nt++)
            #pragma unroll
            for (int i = 0; i < 4; i++) sf[nt][i] = 0.f;

        #pragma unroll
        for (int kt = 0; kt < 2; kt++) {
            int lrow = mbase + ((lane >> 3) & 1) * 8 + (lane & 7);
            int ko   = kt*2 + (lane >> 4);
            uint32_t ah[4], al[4];
            ldsm_x4(ah, qsb + lrow*128 + ((ko ^ (lrow & 7)) << 4));
            ldsm_x4(al, qsb + lrow*128 + (((4 + ko) ^ (lrow & 7)) << 4));
            int krow_l = (lane & 7);
            int kko    = kt*2 + ((lane >> 3) & 1);
            uint32_t kbh[8][2], kbl[8][2];
            #pragma unroll
            for (int nt = 0; nt < 8; nt++) {
                int krow = nt*8 + krow_l;
                ldsm_x2(kbh[nt], ksb + krow*128 + ((kko ^ (krow & 7)) << 4));
                ldsm_x2(kbl[nt], ksb + krow*128 + (((4 + kko) ^ (krow & 7)) << 4));
            }
            #pragma unroll
            for (int nt = 0; nt < 8; nt++) mma16816(sf[nt], ah, kbh[nt]);
            #pragma unroll
            for (int nt = 0; nt < 8; nt++) mma16816(sf[nt], ah, kbl[nt]);
            #pragma unroll
            for (int nt = 0; nt < 8; nt++) mma16816(sf[nt], al, kbh[nt]);
        }

        // ---- epilogue: cosine norm + tau + bias + mask ----
        int rA = mbase + (lane >> 2);
        int rB = rA + 8;
        float qnA = qn_s[rA], qnB = qn_s[rB];
        #pragma unroll
        for (int nt = 0; nt < 8; nt++) {
            int c0 = nt*8 + 2*(lane & 3);
            float2 kn2 = *(float2*)&kn_s[c0];
            int iA = rA*64 + c0, iB = rB*64 + c0;
            float2 tA = *(const float2*)(itp + iA);
            float2 tB = *(const float2*)(itp + iB);
            float2 bA = *(const float2*)(bpp + iA);
            float2 bB = *(const float2*)(bpp + iB);
            float2 mA = *(const float2*)(mpp + iA);
            float2 mB = *(const float2*)(mpp + iB);
            sf[nt][0] = __fdividef(sf[nt][0], fmaxf(qnA*kn2.x, 1e-6f)) * tA.x + bA.x + mA.x;
            sf[nt][1] = __fdividef(sf[nt][1], fmaxf(qnA*kn2.y, 1e-6f)) * tA.y + bA.y + mA.y;
            sf[nt][2] = __fdividef(sf[nt][2], fmaxf(qnB*kn2.x, 1e-6f)) * tB.x + bB.x + mB.x;
            sf[nt][3] = __fdividef(sf[nt][3], fmaxf(qnB*kn2.y, 1e-6f)) * tB.y + bB.y + mB.y;
        }

        // ---- fragment softmax ----
        {
            float mA = -1e30f, mB = -1e30f;
            #pragma unroll
            for (int nt = 0; nt < 8; nt++) {
                mA = fmaxf(mA, fmaxf(sf[nt][0], sf[nt][1]));
                mB = fmaxf(mB, fmaxf(sf[nt][2], sf[nt][3]));
            }
            mA = fmaxf(mA, __shfl_xor_sync(0xffffffffu, mA, 1));
            mA = fmaxf(mA, __shfl_xor_sync(0xffffffffu, mA, 2));
            mB = fmaxf(mB, __shfl_xor_sync(0xffffffffu, mB, 1));
            mB = fmaxf(mB, __shfl_xor_sync(0xffffffffu, mB, 2));
            float sA = 0.f, sB = 0.f;
            #pragma unroll
            for (int nt = 0; nt < 8; nt++) {
                sf[nt][0] = __expf(sf[nt][0] - mA); sA += sf[nt][0];
                sf[nt][1] = __expf(sf[nt][1] - mA); sA += sf[nt][1];
                sf[nt][2] = __expf(sf[nt][2] - mB); sB += sf[nt][2];
                sf[nt][3] = __expf(sf[nt][3] - mB); sB += sf[nt][3];
            }
            sA += __shfl_xor_sync(0xffffffffu, sA, 1);
            sA += __shfl_xor_sync(0xffffffffu, sA, 2);
            sB += __shfl_xor_sync(0xffffffffu, sB, 1);
            sB += __shfl_xor_sync(0xffffffffu, sB, 2);
            float iA2 = __fdividef(1.f, sA);
            float iB2 = __fdividef(1.f, sB);
            #pragma unroll
            for (int nt = 0; nt < 8; nt++) {
                sf[nt][0] *= iA2; sf[nt][1] *= iA2;
                sf[nt][2] *= iB2; sf[nt][3] *= iB2;
            }
        }

        // ---- O = P V ----
        float of[4][4];
        #pragma unroll
        for (int nt = 0; nt < 4; nt++)
            #pragma unroll
            for (int i = 0; i < 4; i++) of[nt][i] = 0.f;

        #pragma unroll
        for (int kt2 = 0; kt2 < 4; kt2++) {
            int ntA = 2*kt2, ntB = 2*kt2 + 1;
            uint32_t pah[4], pal[4];
            float r0, r1;
            pah[0] = pack_hi(sf[ntA][0], sf[ntA][1], r0, r1); pal[0] = pack2(r0, r1);
            pah[1] = pack_hi(sf[ntA][2], sf[ntA][3], r0, r1); pal[1] = pack2(r0, r1);
            pah[2] = pack_hi(sf[ntB][0], sf[ntB][1], r0, r1); pal[2] = pack2(r0, r1);
            pah[3] = pack_hi(sf[ntB][2], sf[ntB][3], r0, r1); pal[3] = pack2(r0, r1);
            int vrow = kt2*16 + (lane & 15);
            int vsw = vrow & 7;
            uint32_t vbh[4][2], vbl[4][2];
            #pragma unroll
            for (int nt2 = 0; nt2 < 4; nt2++) {
                ldsm_x2t(vbh[nt2], vsb + vrow*128 + ((nt2 ^ vsw) << 4));
                ldsm_x2t(vbl[nt2], vsb + vrow*128 + (((4 + nt2) ^ vsw) << 4));
            }
            #pragma unroll
            for (int nt2 = 0; nt2 < 4; nt2++) mma16816(of[nt2], pah, vbh[nt2]);
            #pragma unroll
            for (int nt2 = 0; nt2 < 4; nt2++) mma16816(of[nt2], pah, vbl[nt2]);
            #pragma unroll
            for (int nt2 = 0; nt2 < 4; nt2++) mma16816(of[nt2], pal, vbh[nt2]);
        }

        // ---- store O ----
        {
            float* ob = g_ao + ((size_t)b*NTOK)*DIM + h*HD;
            #pragma unroll
            for (int nt2 = 0; nt2 < 4; nt2++) {
                int c = nt2*8 + 2*(lane & 3);
                *(float2*)(ob + (size_t)rA*DIM + c) = make_float2(of[nt2][0], of[nt2][1]);
                *(float2*)(ob + (size_t)rB*DIM + c) = make_float2(of[nt2][2], of[nt2][3]);
            }
        }
        __syncthreads();
    }
}

// ============================================================
// launch
// ============================================================
extern "C" void kernel_launch(void* const* d_in, const int* in_sizes, int n_in,
                              void* d_out, int out_size)
{
    const float* x      = (const float*)d_in[0];
    const float* KV     = (const float*)d_in[1];
    const float* mask   = (const float*)d_in[2];
    const float* Wq     = (const float*)d_in[3];
    const float* bq     = (const float*)d_in[4];
    const float* Wkv    = (const float*)d_in[5];
    const float* bkv    = (const float*)d_in[6];
    const float* Wp     = (const float*)d_in[7];
    const float* bp     = (const float*)d_in[8];
    const float* cpb_w1 = (const float*)d_in[9];
    const float* cpb_b1 = (const float*)d_in[10];
    const float* cpb_w2 = (const float*)d_in[11];
    const float* cpb_b2 = (const float*)d_in[12];
    const float* tau    = (const float*)d_in[13];
    const float* lri    = (const float*)d_in[14];
    float* out = (float*)d_out;

    const int MT = (BWIN * NTOK) / 128;   // 1024

    prep_w_kernel<<<1024, 256>>>(Wq, Wkv, Wp);
    bias_kernel<<<(NTOK*NTOK + 255)/256, 256>>>(cpb_w1, cpb_b1, cpb_w2, cpb_b2, tau, lri);
    mma_gemm_kernel<<<dim3(2, MT), 256>>>(x,  bq,  nullptr, 256, 0, 0);
    mma_gemm_kernel<<<dim3(4, MT), 256>>>(KV, bkv, nullptr, 512, 1, 65536);
    attn_mma_kernel<<<dim3(512, HEADS), 128>>>(mask);
    mma_gemm_kernel<<<dim3(2, MT), 256>>>(nullptr, bp, out, 256, 2, 196608);
}